// round 4
// baseline (speedup 1.0000x reference)
#include <cuda_runtime.h>
#include <math.h>

#define NN 8
#define C_IN 64
#define C_OUT 64
#define HH 128
#define WW 128
#define KK 4

typedef unsigned long long u64;

// ---------------- packed fp32x2 helpers (Blackwell FFMA2 path) --------------
__device__ __forceinline__ u64 pk2(float lo, float hi) {
    u64 o;
    asm("mov.b64 %0, {%1, %2};" : "=l"(o) : "r"(__float_as_int(lo)), "r"(__float_as_int(hi)));
    return o;
}
__device__ __forceinline__ u64 fma2(u64 a, u64 b, u64 c) {
    u64 d;
    asm("fma.rn.f32x2 %0, %1, %2, %3;" : "=l"(d) : "l"(a), "l"(b), "l"(c));
    return d;
}
__device__ __forceinline__ float2 upk2(u64 v) {
    int lo, hi;
    asm("mov.b64 {%0, %1}, %2;" : "=r"(lo), "=r"(hi) : "l"(v));
    float2 r;
    r.x = __int_as_float(lo);
    r.y = __int_as_float(hi);
    return r;
}

// ---------------- scratch (device globals: no allocations allowed) ----------
__device__ float g_sums[NN][45];                       // 45 class sums per sample
__device__ float g_att[NN][KK];                        // softmax attention
__device__ float g_aggw[NN * C_OUT * C_IN * 9];        // per-sample fused weights (~1.2MB)

// ---------------- kernel 0: zero class-sum scratch ---------------------------
__global__ void zero_sums_kernel() {
    int i = threadIdx.x;
    if (i < NN * 45) ((float*)g_sums)[i] = 0.0f;
}

// ---------------- kernel 1: 45 class sums per sample -------------------------
__global__ void class_sums_kernel(const float* __restrict__ x) {
    int warp = (blockIdx.x * blockDim.x + threadIdx.x) >> 5;
    int lane = threadIdx.x & 31;
    if (warp >= NN * C_IN) return;
    int n = warp / C_IN;
    int c = warp % C_IN;
    const float* p = x + (size_t)(n * C_IN + c) * (HH * WW);

    float T = 0.f, R0 = 0.f, RL = 0.f, Cc0 = 0.f, CcL = 0.f;
    for (int i = lane; i < HH * WW; i += 32) T += p[i];
    for (int i = lane; i < WW; i += 32) {
        R0 += p[i];
        RL += p[(HH - 1) * WW + i];
    }
    for (int h = lane; h < HH; h += 32) {
        Cc0 += p[h * WW];
        CcL += p[h * WW + (WW - 1)];
    }
    #pragma unroll
    for (int o = 16; o; o >>= 1) {
        T   += __shfl_xor_sync(0xffffffffu, T, o);
        R0  += __shfl_xor_sync(0xffffffffu, R0, o);
        RL  += __shfl_xor_sync(0xffffffffu, RL, o);
        Cc0 += __shfl_xor_sync(0xffffffffu, Cc0, o);
        CcL += __shfl_xor_sync(0xffffffffu, CcL, o);
    }
    if (lane == 0) {
        float c00 = p[0];
        float c0L = p[WW - 1];
        float cL0 = p[(HH - 1) * WW];
        float cLL = p[(HH - 1) * WW + (WW - 1)];
        float S[3][3];
        S[0][0] = c00;              S[0][2] = c0L;
        S[0][1] = R0 - c00 - c0L;
        S[2][0] = cL0;              S[2][2] = cLL;
        S[2][1] = RL - cL0 - cLL;
        S[1][0] = Cc0 - c00 - cL0;
        S[1][2] = CcL - c0L - cLL;
        S[1][1] = T - R0 - RL - S[1][0] - S[1][2];
        int cd = (c == 0) ? 0 : (c == 1) ? 1 : (c == C_IN - 2) ? 3 : (c == C_IN - 1) ? 4 : 2;
        float* dst = &g_sums[n][cd * 9];
        #pragma unroll
        for (int i = 0; i < 9; i++) atomicAdd(&dst[i], S[i / 3][i % 3]);
    }
}

// ---------------- kernel 2: logits from class sums + softmax -----------------
__global__ void logits_softmax_kernel(const float* __restrict__ net0_w,
                                      const float* __restrict__ net0_b,
                                      const float* __restrict__ net1_w,
                                      const float* __restrict__ net1_b,
                                      const float* __restrict__ net2_w,
                                      const float* __restrict__ net2_b) {
    __shared__ float lg[NN][KK];
    int t = threadIdx.x;
    if (t < NN * KK) {
        int n = t / KK, k = t % KK;
        float S[5][3][3];
        #pragma unroll
        for (int i = 0; i < 45; i++) ((float*)S)[i] = g_sums[n][i];
        float Stot = 0.f;
        #pragma unroll
        for (int i = 0; i < 45; i++) Stot += ((float*)S)[i];

        const float mh[3][3]  = {{0,1,1},{1,1,1},{1,1,0}};
        const float m1d[3][5] = {{0,1,1,1,1},{1,1,1,1,1},{1,1,1,1,0}};
        const float m2d[5][5] = {{0,0,1,1,1},{0,1,1,1,1},{1,1,1,1,1},{1,1,1,1,0},{1,1,1,0,0}};
        const float invV = 1.0f / (float)(C_IN * HH * WW);

        float acc = net0_b[k] + net1_b[k] + net2_b[k] + net0_w[k] * Stot * invV;

        float s1 = 0.f;
        for (int td = 0; td < 3; td++) {
            float B[3][3];
            for (int ch = 0; ch < 3; ch++)
                for (int cw = 0; cw < 3; cw++) {
                    float v = 0.f;
                    for (int cd = 0; cd < 5; cd++) v += m1d[td][cd] * S[cd][ch][cw];
                    B[ch][cw] = v;
                }
            for (int th = 0; th < 3; th++)
                for (int tw = 0; tw < 3; tw++) {
                    float box = 0.f;
                    for (int ch = 0; ch < 3; ch++)
                        for (int cw = 0; cw < 3; cw++)
                            box += mh[th][ch] * mh[tw][cw] * B[ch][cw];
                    s1 += net1_w[k * 27 + td * 9 + th * 3 + tw] * box;
                }
        }
        float s2 = 0.f;
        for (int td = 0; td < 5; td++) {
            float B[3][3];
            for (int ch = 0; ch < 3; ch++)
                for (int cw = 0; cw < 3; cw++) {
                    float v = 0.f;
                    for (int cd = 0; cd < 5; cd++) v += m2d[td][cd] * S[cd][ch][cw];
                    B[ch][cw] = v;
                }
            for (int th = 0; th < 3; th++)
                for (int tw = 0; tw < 3; tw++) {
                    float box = 0.f;
                    for (int ch = 0; ch < 3; ch++)
                        for (int cw = 0; cw < 3; cw++)
                            box += mh[th][ch] * mh[tw][cw] * B[ch][cw];
                    s2 += net2_w[k * 45 + td * 9 + th * 3 + tw] * box;
                }
        }
        acc += (s1 + s2) * invV;
        lg[n][k] = acc;
    }
    __syncthreads();
    if (t < NN * KK) {
        int n = t / KK, k = t % KK;
        float m = lg[n][0];
        #pragma unroll
        for (int j = 1; j < KK; j++) m = fmaxf(m, lg[n][j]);
        float sum = 0.f;
        #pragma unroll
        for (int j = 0; j < KK; j++) sum += expf(lg[n][j] - m);
        g_att[n][k] = expf(lg[n][k] - m) / sum;
    }
}

// ---------------- kernel 3: per-sample fused weight = conv_w + sum_k att*w_k -
__global__ void agg_weights_kernel(const float* __restrict__ weight,
                                   const float* __restrict__ conv_w) {
    const int per_n4 = C_OUT * C_IN * 9 / 4;  // 9216 float4 per sample
    int idx = blockIdx.x * blockDim.x + threadIdx.x;
    if (idx >= NN * per_n4) return;
    int n = idx / per_n4;
    int r = idx - n * per_n4;
    float a0 = g_att[n][0], a1 = g_att[n][1], a2 = g_att[n][2], a3 = g_att[n][3];
    float4 base = ((const float4*)conv_w)[r];
    const float4* w4 = (const float4*)weight;
    float4 w0 = w4[0 * per_n4 + r];
    float4 w1 = w4[1 * per_n4 + r];
    float4 w2 = w4[2 * per_n4 + r];
    float4 w3 = w4[3 * per_n4 + r];
    float4 o;
    o.x = base.x + a0 * w0.x + a1 * w1.x + a2 * w2.x + a3 * w3.x;
    o.y = base.y + a0 * w0.y + a1 * w1.y + a2 * w2.y + a3 * w3.y;
    o.z = base.z + a0 * w0.z + a1 * w1.z + a2 * w2.z + a3 * w3.z;
    o.w = base.w + a0 * w0.w + a1 * w1.w + a2 * w2.w + a3 * w3.w;
    ((float4*)g_aggw)[(size_t)n * per_n4 + r] = o;
}

// ---------------- kernel 4: fused direct conv2d (3x3, pad1) + bias -----------
// Packed fp32x2 (FFMA2) version: 2 FMAs per fma-pipe issue slot.
// Block tile: 32 co x 16 h x 32 w, one sample. C_IN chunks of 8 in SMEM.
__global__ __launch_bounds__(256, 2)
void conv_fused_kernel(const float* __restrict__ x,
                       const float* __restrict__ conv_b,
                       float* __restrict__ out) {
    const int CI_C = 8;
    __shared__ float xs[CI_C][18][36];
    __shared__ float wsm[32][CI_C][9];

    int w0 = blockIdx.x * 32;
    int h0 = blockIdx.y * 16;
    int n   = blockIdx.z >> 1;
    int co0 = (blockIdx.z & 1) * 32;

    int tid = threadIdx.x;
    int tc = tid >> 6;         // 0..3  (8 co each)
    int th = (tid >> 3) & 7;   // 0..7  (2 h each)
    int tw = tid & 7;          // 0..7  (4 w each = 2 packed pairs)

    // acc2[j][r][p]: co=tc*8+j, h=h0+th*2+r, w pair p covers w0+tw*4+{2p,2p+1}
    u64 acc2[8][2][2];
    #pragma unroll
    for (int j = 0; j < 8; j++)
        #pragma unroll
        for (int r = 0; r < 2; r++) {
            acc2[j][r][0] = 0ull;
            acc2[j][r][1] = 0ull;
        }

    const float* xn = x + (size_t)n * C_IN * HH * WW;
    const float* wn = g_aggw + (size_t)n * C_OUT * C_IN * 9;

    for (int cib = 0; cib < C_IN; cib += CI_C) {
        // --- load x tile with halo (18 x 34), zero padding outside ---
        for (int i = tid; i < CI_C * 18 * 34; i += 256) {
            int ci = i / (18 * 34);
            int rem = i - ci * (18 * 34);
            int rr = rem / 34;
            int cc = rem - rr * 34;
            int gh = h0 - 1 + rr;
            int gw = w0 - 1 + cc;
            float v = 0.f;
            if ((unsigned)gh < (unsigned)HH && (unsigned)gw < (unsigned)WW)
                v = xn[(size_t)(cib + ci) * (HH * WW) + gh * WW + gw];
            xs[ci][rr][cc] = v;
        }
        // --- load weight chunk ---
        for (int i = tid; i < 32 * CI_C * 9; i += 256) {
            int co = i / (CI_C * 9);
            int rem = i - co * (CI_C * 9);
            int ci = rem / 9;
            int kk = rem - ci * 9;
            wsm[co][ci][kk] = wn[(size_t)(co0 + co) * (C_IN * 9) + (cib + ci) * 9 + kk];
        }
        __syncthreads();

        #pragma unroll
        for (int ci = 0; ci < CI_C; ci++) {
            #pragma unroll
            for (int kh = 0; kh < 3; kh++) {
                float xr[2][6];
                #pragma unroll
                for (int r = 0; r < 2; r++)
                    #pragma unroll
                    for (int c = 0; c < 6; c++)
                        xr[r][c] = xs[ci][th * 2 + r + kh][tw * 4 + c];
                // pre-pack overlapping pairs: xp[r][i] = {xr[i], xr[i+1]}
                u64 xp[2][5];
                #pragma unroll
                for (int r = 0; r < 2; r++)
                    #pragma unroll
                    for (int i = 0; i < 5; i++)
                        xp[r][i] = pk2(xr[r][i], xr[r][i + 1]);
                #pragma unroll
                for (int kw = 0; kw < 3; kw++) {
                    #pragma unroll
                    for (int j = 0; j < 8; j++) {
                        float wv = wsm[tc * 8 + j][ci][kh * 3 + kw];
                        u64 w2 = pk2(wv, wv);
                        #pragma unroll
                        for (int r = 0; r < 2; r++) {
                            acc2[j][r][0] = fma2(xp[r][kw],     w2, acc2[j][r][0]);
                            acc2[j][r][1] = fma2(xp[r][kw + 2], w2, acc2[j][r][1]);
                        }
                    }
                }
            }
        }
        __syncthreads();
    }

    // --- epilogue: add bias, vectorized store ---
    #pragma unroll
    for (int j = 0; j < 8; j++) {
        int co = co0 + tc * 8 + j;
        float b = conv_b[co];
        #pragma unroll
        for (int r = 0; r < 2; r++) {
            int h = h0 + th * 2 + r;
            int w = w0 + tw * 4;
            float2 p0 = upk2(acc2[j][r][0]);
            float2 p1 = upk2(acc2[j][r][1]);
            float4 v;
            v.x = p0.x + b;
            v.y = p0.y + b;
            v.z = p1.x + b;
            v.w = p1.y + b;
            *(float4*)&out[((size_t)(n * C_OUT + co) * HH + h) * WW + w] = v;
        }
    }
}

// ---------------- launch ------------------------------------------------------
extern "C" void kernel_launch(void* const* d_in, const int* in_sizes, int n_in,
                              void* d_out, int out_size) {
    const float* x      = (const float*)d_in[0];
    const float* weight = (const float*)d_in[1];
    const float* conv_w = (const float*)d_in[2];
    const float* conv_b = (const float*)d_in[3];
    const float* net0_w = (const float*)d_in[4];
    const float* net0_b = (const float*)d_in[5];
    const float* net1_w = (const float*)d_in[6];
    const float* net1_b = (const float*)d_in[7];
    const float* net2_w = (const float*)d_in[8];
    const float* net2_b = (const float*)d_in[9];
    float* out = (float*)d_out;

    zero_sums_kernel<<<1, 512>>>();
    class_sums_kernel<<<(NN * C_IN * 32) / 256, 256>>>(x);
    logits_softmax_kernel<<<1, 32>>>(net0_w, net0_b, net1_w, net1_b, net2_w, net2_b);
    agg_weights_kernel<<<(NN * C_OUT * C_IN * 9 / 4 + 255) / 256, 256>>>(weight, conv_w);
    conv_fused_kernel<<<dim3(WW / 32, HH / 16, NN * 2), 256>>>(x, conv_b, out);
}

// round 5
// speedup vs baseline: 2.3389x; 2.3389x over previous
#include <cuda_runtime.h>
#include <cuda_bf16.h>
#include <math.h>

#define NN 8
#define C_IN 64
#define C_OUT 64
#define HH 128
#define WW 128
#define KK 4
#define CIP 72          // padded ci pitch (bf16 elems) -> conflict-free ldmatrix

typedef unsigned int u32;

// ---------------- scratch (device globals; no allocations allowed) ----------
__device__ float g_sums[NN][45];
__device__ float g_att[NN][KK];
__device__ __nv_bfloat16 g_wh[NN * 9 * C_OUT * C_IN];   // fused weight hi, [n][tap][co][ci]
__device__ __nv_bfloat16 g_wl[NN * 9 * C_OUT * C_IN];   // fused weight lo

// ---------------- kernel 0: zero class-sum scratch --------------------------
__global__ void zero_sums_kernel() {
    int i = threadIdx.x;
    if (i < NN * 45) ((float*)g_sums)[i] = 0.0f;
}

// ---------------- kernel 1: 45 class sums (quarter-channel warps) -----------
__global__ void class_sums_kernel(const float* __restrict__ x) {
    int gwarp = (blockIdx.x * blockDim.x + threadIdx.x) >> 5;   // 0..2047
    int lane = threadIdx.x & 31;
    int ch = gwarp >> 2, q = gwarp & 3;
    int n = ch >> 6, c = ch & 63;
    const float* p = x + (size_t)(n * C_IN + c) * (HH * WW);
    const float* pr = p + q * 32 * WW;

    float T = 0.f;
    #pragma unroll 4
    for (int i = lane; i < 32 * WW; i += 32) T += pr[i];
    float R0 = 0.f, RL = 0.f;
    if (q == 0) for (int i = lane; i < WW; i += 32) R0 += p[i];
    if (q == 3) for (int i = lane; i < WW; i += 32) RL += p[(HH - 1) * WW + i];
    int h = q * 32 + lane;                       // one row per lane
    float C0 = p[h * WW], CL = p[h * WW + WW - 1];

    #pragma unroll
    for (int o = 16; o; o >>= 1) {
        T  += __shfl_xor_sync(0xffffffffu, T, o);
        R0 += __shfl_xor_sync(0xffffffffu, R0, o);
        RL += __shfl_xor_sync(0xffffffffu, RL, o);
        C0 += __shfl_xor_sync(0xffffffffu, C0, o);
        CL += __shfl_xor_sync(0xffffffffu, CL, o);
    }
    float c00 = (q == 0) ? p[0] : 0.f;
    float c0L = (q == 0) ? p[WW - 1] : 0.f;
    float cL0 = (q == 3) ? p[(HH - 1) * WW] : 0.f;
    float cLL = (q == 3) ? p[HH * WW - 1] : 0.f;
    float S[9];
    S[0] = c00;  S[2] = c0L;
    S[1] = R0 - c00 - c0L;
    S[6] = cL0;  S[8] = cLL;
    S[7] = RL - cL0 - cLL;
    S[3] = C0 - c00 - cL0;
    S[5] = CL - c0L - cLL;
    S[4] = T - R0 - RL - S[3] - S[5];
    int cd = (c == 0) ? 0 : (c == 1) ? 1 : (c == C_IN - 2) ? 3 : (c == C_IN - 1) ? 4 : 2;
    if (lane < 9) atomicAdd(&g_sums[n][cd * 9 + lane], S[lane]);
}

// ---------------- kernel 2: logits from class sums + softmax ----------------
__global__ void logits_softmax_kernel(const float* __restrict__ net0_w,
                                      const float* __restrict__ net0_b,
                                      const float* __restrict__ net1_w,
                                      const float* __restrict__ net1_b,
                                      const float* __restrict__ net2_w,
                                      const float* __restrict__ net2_b) {
    __shared__ float lg[NN][KK];
    int t = threadIdx.x;
    if (t < NN * KK) {
        int n = t / KK, k = t % KK;
        float S[5][3][3];
        #pragma unroll
        for (int i = 0; i < 45; i++) ((float*)S)[i] = g_sums[n][i];
        float Stot = 0.f;
        #pragma unroll
        for (int i = 0; i < 45; i++) Stot += ((float*)S)[i];

        const float mh[3][3]  = {{0,1,1},{1,1,1},{1,1,0}};
        const float m1d[3][5] = {{0,1,1,1,1},{1,1,1,1,1},{1,1,1,1,0}};
        const float m2d[5][5] = {{0,0,1,1,1},{0,1,1,1,1},{1,1,1,1,1},{1,1,1,1,0},{1,1,1,0,0}};
        const float invV = 1.0f / (float)(C_IN * HH * WW);

        float acc = net0_b[k] + net1_b[k] + net2_b[k] + net0_w[k] * Stot * invV;

        float s1 = 0.f;
        for (int td = 0; td < 3; td++) {
            float B[3][3];
            for (int ch = 0; ch < 3; ch++)
                for (int cw = 0; cw < 3; cw++) {
                    float v = 0.f;
                    for (int cd = 0; cd < 5; cd++) v += m1d[td][cd] * S[cd][ch][cw];
                    B[ch][cw] = v;
                }
            for (int th = 0; th < 3; th++)
                for (int tw = 0; tw < 3; tw++) {
                    float box = 0.f;
                    for (int ch = 0; ch < 3; ch++)
                        for (int cw = 0; cw < 3; cw++)
                            box += mh[th][ch] * mh[tw][cw] * B[ch][cw];
                    s1 += net1_w[k * 27 + td * 9 + th * 3 + tw] * box;
                }
        }
        float s2 = 0.f;
        for (int td = 0; td < 5; td++) {
            float B[3][3];
            for (int ch = 0; ch < 3; ch++)
                for (int cw = 0; cw < 3; cw++) {
                    float v = 0.f;
                    for (int cd = 0; cd < 5; cd++) v += m2d[td][cd] * S[cd][ch][cw];
                    B[ch][cw] = v;
                }
            for (int th = 0; th < 3; th++)
                for (int tw = 0; tw < 3; tw++) {
                    float box = 0.f;
                    for (int ch = 0; ch < 3; ch++)
                        for (int cw = 0; cw < 3; cw++)
                            box += mh[th][ch] * mh[tw][cw] * B[ch][cw];
                    s2 += net2_w[k * 45 + td * 9 + th * 3 + tw] * box;
                }
        }
        acc += (s1 + s2) * invV;
        lg[n][k] = acc;
    }
    __syncthreads();
    if (t < NN * KK) {
        int n = t / KK, k = t % KK;
        float m = lg[n][0];
        #pragma unroll
        for (int j = 1; j < KK; j++) m = fmaxf(m, lg[n][j]);
        float sum = 0.f;
        #pragma unroll
        for (int j = 0; j < KK; j++) sum += expf(lg[n][j] - m);
        g_att[n][k] = expf(lg[n][k] - m) / sum;
    }
}

// ---------------- kernel 3: fused weight -> bf16 hi/lo in [n][tap][co][ci] --
__global__ void agg_weights_kernel(const float* __restrict__ weight,
                                   const float* __restrict__ conv_w) {
    int idx = blockIdx.x * blockDim.x + threadIdx.x;
    if (idx >= NN * 9 * C_OUT * C_IN) return;
    int n  = idx / (9 * C_OUT * C_IN);
    int r  = idx - n * (9 * C_OUT * C_IN);
    int t  = r / (C_OUT * C_IN);
    int r2 = r - t * (C_OUT * C_IN);
    int co = r2 >> 6, ci = r2 & 63;
    int widx = (co * C_IN + ci) * 9 + t;
    const int PER_K = C_OUT * C_IN * 9;
    float v = conv_w[widx]
            + g_att[n][0] * weight[0 * PER_K + widx]
            + g_att[n][1] * weight[1 * PER_K + widx]
            + g_att[n][2] * weight[2 * PER_K + widx]
            + g_att[n][3] * weight[3 * PER_K + widx];
    __nv_bfloat16 hi = __float2bfloat16_rn(v);
    __nv_bfloat16 lo = __float2bfloat16_rn(v - __bfloat162float(hi));
    g_wh[idx] = hi;
    g_wl[idx] = lo;
}

// ---------------- kernel 4: tensor-core implicit-GEMM conv ------------------
__device__ __forceinline__ u32 su32(const void* p) {
    return (u32)__cvta_generic_to_shared(p);
}

#define LDSM4(R, ADDR)                                                         \
    asm volatile("ldmatrix.sync.aligned.m8n8.x4.shared.b16 {%0,%1,%2,%3}, [%4];" \
                 : "=r"((R)[0]), "=r"((R)[1]), "=r"((R)[2]), "=r"((R)[3])      \
                 : "r"(ADDR))

#define MMA_BF16(C, A, B0, B1)                                                 \
    asm volatile("mma.sync.aligned.m16n8k16.row.col.f32.bf16.bf16.f32 "       \
                 "{%0,%1,%2,%3}, {%4,%5,%6,%7}, {%8,%9}, {%0,%1,%2,%3};"      \
                 : "+f"((C)[0]), "+f"((C)[1]), "+f"((C)[2]), "+f"((C)[3])     \
                 : "r"((A)[0]), "r"((A)[1]), "r"((A)[2]), "r"((A)[3]),        \
                   "r"(B0), "r"(B1))

// smem (bf16 elems):
//  xh [18*18][CIP], xl [18*18][CIP]   (channel-last x tile hi/lo, halo 18x18)
//  Bs [3 taps][2 splits][64 co][CIP]  (weight group, reloaded per kh)
#define XS_ELEMS (18 * 18 * CIP)
#define BS_ELEMS (3 * 2 * C_OUT * CIP)
#define SMEM_BYTES ((2 * XS_ELEMS + BS_ELEMS) * 2)

__global__ __launch_bounds__(256, 1)
void conv_mma_kernel(const float* __restrict__ x,
                     const float* __restrict__ conv_b,
                     float* __restrict__ out) {
    extern __shared__ __nv_bfloat16 sm[];
    __nv_bfloat16* xh = sm;
    __nv_bfloat16* xl = sm + XS_ELEMS;
    __nv_bfloat16* Bs = sm + 2 * XS_ELEMS;

    int w0 = blockIdx.x * 16, h0 = blockIdx.y * 16, n = blockIdx.z;
    int tid = threadIdx.x, warp = tid >> 5, lane = tid & 31;

    // --- stage x tile (18x18 halo, all 64 ci), convert to bf16 hi/lo --------
    const float* xn = x + (size_t)n * C_IN * HH * WW;
    for (int i = tid; i < 18 * 18 * C_IN; i += 256) {
        int ci = i / 324;
        int rem = i - ci * 324;
        int r = rem / 18, c = rem - r * 18;
        int gh = h0 - 1 + r, gw = w0 - 1 + c;
        float v = 0.f;
        if ((unsigned)gh < (unsigned)HH && (unsigned)gw < (unsigned)WW)
            v = xn[ci * (HH * WW) + gh * WW + gw];
        __nv_bfloat16 hi = __float2bfloat16_rn(v);
        __nv_bfloat16 lo = __float2bfloat16_rn(v - __bfloat162float(hi));
        int o = (r * 18 + c) * CIP + ci;
        xh[o] = hi;
        xl[o] = lo;
    }

    float acc[2][8][4];
    #pragma unroll
    for (int mf = 0; mf < 2; mf++)
        #pragma unroll
        for (int nf = 0; nf < 8; nf++)
            #pragma unroll
            for (int r = 0; r < 4; r++) acc[mf][nf][r] = 0.f;

    // ldmatrix lane geometry
    int arow = lane & 15;             // A: w_local row
    int acb  = lane >> 4;             // A: k column block
    int brow = (lane & 7) + ((lane >> 4) << 3);   // B: co row within 16
    int bcb  = (lane >> 3) & 1;                   // B: k column block

    u32 xh_s = su32(xh), xl_s = su32(xl), bs_s = su32(Bs);

    const __nv_bfloat16* whn = g_wh + (size_t)n * 9 * C_OUT * C_IN;
    const __nv_bfloat16* wln = g_wl + (size_t)n * 9 * C_OUT * C_IN;

    for (int g = 0; g < 3; g++) {                 // g == kh
        __syncthreads();
        // load B group: taps {g*3 .. g*3+2}, both splits, vectorized
        for (int i = tid; i < 3072; i += 256) {
            int split = i / 1536;
            int r2 = i - split * 1536;
            int tloc = r2 >> 9;
            int rr = r2 & 511;
            int co = rr >> 3, q = rr & 7;
            const __nv_bfloat16* src = split ? wln : whn;
            uint4 v = *(const uint4*)(src + ((size_t)((g * 3 + tloc) * C_OUT + co)) * C_IN + q * 8);
            *(uint4*)&Bs[((tloc * 2 + split) * C_OUT + co) * CIP + q * 8] = v;
        }
        __syncthreads();

        #pragma unroll
        for (int tl = 0; tl < 3; tl++) {          // tl == kw
            u32 a_base0 = (u32)(((2 * warp + 0 + g) * 18 + arow + tl) * CIP + acb * 8) * 2;
            u32 a_base1 = (u32)(((2 * warp + 1 + g) * 18 + arow + tl) * CIP + acb * 8) * 2;
            #pragma unroll
            for (int kc = 0; kc < 4; kc++) {
                u32 ah0[4], ah1[4], al0[4], al1[4];
                u32 ko = kc * 32;                 // kc*16 elems * 2B
                LDSM4(ah0, xh_s + a_base0 + ko);
                LDSM4(ah1, xh_s + a_base1 + ko);
                LDSM4(al0, xl_s + a_base0 + ko);
                LDSM4(al1, xl_s + a_base1 + ko);
                u32 bh[16], bl[16];
                #pragma unroll
                for (int p = 0; p < 4; p++) {
                    u32 oh = (u32)((((tl * 2 + 0) * C_OUT + brow + p * 16) * CIP) + bcb * 8) * 2 + ko;
                    u32 ol = (u32)((((tl * 2 + 1) * C_OUT + brow + p * 16) * CIP) + bcb * 8) * 2 + ko;
                    LDSM4(&bh[4 * p], bs_s + oh);
                    LDSM4(&bl[4 * p], bs_s + ol);
                }
                // product 0: xh * wh
                #pragma unroll
                for (int nf = 0; nf < 8; nf++) {
                    int bi = (nf >> 1) * 4 + (nf & 1) * 2;
                    MMA_BF16(acc[0][nf], ah0, bh[bi], bh[bi + 1]);
                    MMA_BF16(acc[1][nf], ah1, bh[bi], bh[bi + 1]);
                }
                // product 1: xl * wh
                #pragma unroll
                for (int nf = 0; nf < 8; nf++) {
                    int bi = (nf >> 1) * 4 + (nf & 1) * 2;
                    MMA_BF16(acc[0][nf], al0, bh[bi], bh[bi + 1]);
                    MMA_BF16(acc[1][nf], al1, bh[bi], bh[bi + 1]);
                }
                // product 2: xh * wl
                #pragma unroll
                for (int nf = 0; nf < 8; nf++) {
                    int bi = (nf >> 1) * 4 + (nf & 1) * 2;
                    MMA_BF16(acc[0][nf], ah0, bl[bi], bl[bi + 1]);
                    MMA_BF16(acc[1][nf], ah1, bl[bi], bl[bi + 1]);
                }
            }
        }
    }

    // --- epilogue: C frag rows = w_local, cols = co; add bias ---------------
    int gg = lane >> 2, tig = lane & 3;
    #pragma unroll
    for (int mf = 0; mf < 2; mf++) {
        int h = h0 + 2 * warp + mf;
        #pragma unroll
        for (int nf = 0; nf < 8; nf++) {
            int co = nf * 8 + tig * 2;
            float b0 = conv_b[co], b1 = conv_b[co + 1];
            size_t base = ((size_t)(n * C_OUT + co) * HH + h) * WW + w0;
            out[base + gg]                 = acc[mf][nf][0] + b0;
            out[base + HH * WW + gg]       = acc[mf][nf][1] + b1;
            out[base + gg + 8]             = acc[mf][nf][2] + b0;
            out[base + HH * WW + gg + 8]   = acc[mf][nf][3] + b1;
        }
    }
}

// ---------------- launch -----------------------------------------------------
extern "C" void kernel_launch(void* const* d_in, const int* in_sizes, int n_in,
                              void* d_out, int out_size) {
    const float* x      = (const float*)d_in[0];
    const float* weight = (const float*)d_in[1];
    const float* conv_w = (const float*)d_in[2];
    const float* conv_b = (const float*)d_in[3];
    const float* net0_w = (const float*)d_in[4];
    const float* net0_b = (const float*)d_in[5];
    const float* net1_w = (const float*)d_in[6];
    const float* net1_b = (const float*)d_in[7];
    const float* net2_w = (const float*)d_in[8];
    const float* net2_b = (const float*)d_in[9];
    float* out = (float*)d_out;

    static int smem_set = 0;
    if (!smem_set) {
        cudaFuncSetAttribute(conv_mma_kernel,
                             cudaFuncAttributeMaxDynamicSharedMemorySize, SMEM_BYTES);
        smem_set = 1;
    }

    zero_sums_kernel<<<1, 512>>>();
    class_sums_kernel<<<256, 256>>>(x);
    logits_softmax_kernel<<<1, 32>>>(net0_w, net0_b, net1_w, net1_b, net2_w, net2_b);
    agg_weights_kernel<<<(NN * 9 * C_OUT * C_IN + 255) / 256, 256>>>(weight, conv_w);
    conv_mma_kernel<<<dim3(WW / 16, HH / 16, NN), 256, SMEM_BYTES>>>(x, conv_b, out);
}

// round 6
// speedup vs baseline: 3.3561x; 1.4349x over previous
#include <cuda_runtime.h>
#include <cuda_fp16.h>
#include <math.h>

#define NN 8
#define C_IN 64
#define C_OUT 64
#define HH 128
#define WW 128
#define KK 4

typedef unsigned int u32;

// ---------------- scratch (device globals; no allocations allowed) ----------
__device__ float g_sums[NN][45];
__device__ float g_att[NN][KK];
__device__ __half g_wh[NN * 9 * C_OUT * C_IN];   // fused weight fp16, [n][tap][co][ci]

// ---------------- kernel 0: zero class-sum scratch --------------------------
__global__ void zero_sums_kernel() {
    int i = threadIdx.x;
    if (i < NN * 45) ((float*)g_sums)[i] = 0.0f;
}

// ---------------- kernel 1: 45 class sums (quarter-channel warps) -----------
__global__ void class_sums_kernel(const float* __restrict__ x) {
    int gwarp = (blockIdx.x * blockDim.x + threadIdx.x) >> 5;   // 0..2047
    int lane = threadIdx.x & 31;
    int ch = gwarp >> 2, q = gwarp & 3;
    int n = ch >> 6, c = ch & 63;
    const float* p = x + (size_t)(n * C_IN + c) * (HH * WW);
    const float* pr = p + q * 32 * WW;

    float T = 0.f;
    #pragma unroll 4
    for (int i = lane; i < 32 * WW; i += 32) T += pr[i];
    float R0 = 0.f, RL = 0.f;
    if (q == 0) for (int i = lane; i < WW; i += 32) R0 += p[i];
    if (q == 3) for (int i = lane; i < WW; i += 32) RL += p[(HH - 1) * WW + i];
    int h = q * 32 + lane;
    float C0 = p[h * WW], CL = p[h * WW + WW - 1];

    #pragma unroll
    for (int o = 16; o; o >>= 1) {
        T  += __shfl_xor_sync(0xffffffffu, T, o);
        R0 += __shfl_xor_sync(0xffffffffu, R0, o);
        RL += __shfl_xor_sync(0xffffffffu, RL, o);
        C0 += __shfl_xor_sync(0xffffffffu, C0, o);
        CL += __shfl_xor_sync(0xffffffffu, CL, o);
    }
    float c00 = (q == 0) ? p[0] : 0.f;
    float c0L = (q == 0) ? p[WW - 1] : 0.f;
    float cL0 = (q == 3) ? p[(HH - 1) * WW] : 0.f;
    float cLL = (q == 3) ? p[HH * WW - 1] : 0.f;
    float S[9];
    S[0] = c00;  S[2] = c0L;
    S[1] = R0 - c00 - c0L;
    S[6] = cL0;  S[8] = cLL;
    S[7] = RL - cL0 - cLL;
    S[3] = C0 - c00 - cL0;
    S[5] = CL - c0L - cLL;
    S[4] = T - R0 - RL - S[3] - S[5];
    int cd = (c == 0) ? 0 : (c == 1) ? 1 : (c == C_IN - 2) ? 3 : (c == C_IN - 1) ? 4 : 2;
    if (lane < 9) atomicAdd(&g_sums[n][cd * 9 + lane], S[lane]);
}

// ---------------- kernel 2: logits from class sums + softmax ----------------
__global__ void logits_softmax_kernel(const float* __restrict__ net0_w,
                                      const float* __restrict__ net0_b,
                                      const float* __restrict__ net1_w,
                                      const float* __restrict__ net1_b,
                                      const float* __restrict__ net2_w,
                                      const float* __restrict__ net2_b) {
    __shared__ float lg[NN][KK];
    int t = threadIdx.x;
    if (t < NN * KK) {
        int n = t / KK, k = t % KK;
        float S[5][3][3];
        #pragma unroll
        for (int i = 0; i < 45; i++) ((float*)S)[i] = g_sums[n][i];
        float Stot = 0.f;
        #pragma unroll
        for (int i = 0; i < 45; i++) Stot += ((float*)S)[i];

        const float mh[3][3]  = {{0,1,1},{1,1,1},{1,1,0}};
        const float m1d[3][5] = {{0,1,1,1,1},{1,1,1,1,1},{1,1,1,1,0}};
        const float m2d[5][5] = {{0,0,1,1,1},{0,1,1,1,1},{1,1,1,1,1},{1,1,1,1,0},{1,1,1,0,0}};
        const float invV = 1.0f / (float)(C_IN * HH * WW);

        float acc = net0_b[k] + net1_b[k] + net2_b[k] + net0_w[k] * Stot * invV;

        float s1 = 0.f;
        for (int td = 0; td < 3; td++) {
            float B[3][3];
            for (int ch = 0; ch < 3; ch++)
                for (int cw = 0; cw < 3; cw++) {
                    float v = 0.f;
                    for (int cd = 0; cd < 5; cd++) v += m1d[td][cd] * S[cd][ch][cw];
                    B[ch][cw] = v;
                }
            for (int th = 0; th < 3; th++)
                for (int tw = 0; tw < 3; tw++) {
                    float box = 0.f;
                    for (int ch = 0; ch < 3; ch++)
                        for (int cw = 0; cw < 3; cw++)
                            box += mh[th][ch] * mh[tw][cw] * B[ch][cw];
                    s1 += net1_w[k * 27 + td * 9 + th * 3 + tw] * box;
                }
        }
        float s2 = 0.f;
        for (int td = 0; td < 5; td++) {
            float B[3][3];
            for (int ch = 0; ch < 3; ch++)
                for (int cw = 0; cw < 3; cw++) {
                    float v = 0.f;
                    for (int cd = 0; cd < 5; cd++) v += m2d[td][cd] * S[cd][ch][cw];
                    B[ch][cw] = v;
                }
            for (int th = 0; th < 3; th++)
                for (int tw = 0; tw < 3; tw++) {
                    float box = 0.f;
                    for (int ch = 0; ch < 3; ch++)
                        for (int cw = 0; cw < 3; cw++)
                            box += mh[th][ch] * mh[tw][cw] * B[ch][cw];
                    s2 += net2_w[k * 45 + td * 9 + th * 3 + tw] * box;
                }
        }
        acc += (s1 + s2) * invV;
        lg[n][k] = acc;
    }
    __syncthreads();
    if (t < NN * KK) {
        int n = t / KK, k = t % KK;
        float m = lg[n][0];
        #pragma unroll
        for (int j = 1; j < KK; j++) m = fmaxf(m, lg[n][j]);
        float sum = 0.f;
        #pragma unroll
        for (int j = 0; j < KK; j++) sum += expf(lg[n][j] - m);
        g_att[n][k] = expf(lg[n][k] - m) / sum;
    }
}

// ---------------- kernel 3: fused weight -> fp16 in [n][tap][co][ci] --------
__global__ void agg_weights_kernel(const float* __restrict__ weight,
                                   const float* __restrict__ conv_w) {
    int idx = blockIdx.x * blockDim.x + threadIdx.x;
    if (idx >= NN * 9 * C_OUT * C_IN) return;
    int n  = idx / (9 * C_OUT * C_IN);
    int r  = idx - n * (9 * C_OUT * C_IN);
    int t  = r / (C_OUT * C_IN);
    int r2 = r - t * (C_OUT * C_IN);
    int co = r2 >> 6, ci = r2 & 63;
    int widx = (co * C_IN + ci) * 9 + t;
    const int PER_K = C_OUT * C_IN * 9;
    float v = conv_w[widx]
            + g_att[n][0] * weight[0 * PER_K + widx]
            + g_att[n][1] * weight[1 * PER_K + widx]
            + g_att[n][2] * weight[2 * PER_K + widx]
            + g_att[n][3] * weight[3 * PER_K + widx];
    g_wh[idx] = __float2half_rn(v);
}

// ---------------- kernel 4: tensor-core implicit-GEMM conv (fp16 2-prod) ----
__device__ __forceinline__ u32 su32(const void* p) {
    return (u32)__cvta_generic_to_shared(p);
}

#define LDSM4(R, ADDR)                                                         \
    asm volatile("ldmatrix.sync.aligned.m8n8.x4.shared.b16 {%0,%1,%2,%3}, [%4];" \
                 : "=r"((R)[0]), "=r"((R)[1]), "=r"((R)[2]), "=r"((R)[3])      \
                 : "r"(ADDR))

#define MMA_FP16(C, A, B0, B1)                                                 \
    asm volatile("mma.sync.aligned.m16n8k16.row.col.f32.f16.f16.f32 "         \
                 "{%0,%1,%2,%3}, {%4,%5,%6,%7}, {%8,%9}, {%0,%1,%2,%3};"      \
                 : "+f"((C)[0]), "+f"((C)[1]), "+f"((C)[2]), "+f"((C)[3])     \
                 : "r"((A)[0]), "r"((A)[1]), "r"((A)[2]), "r"((A)[3]),        \
                   "r"(B0), "r"(B1))

// smem layout (bytes), 128B rows + XOR swizzle (chunk' = chunk ^ (row&7)):
//   xh: 324 rows (18x18 spatial) x 128B (64 ci fp16)    = 41472 B
//   xl: same                                            = 41472 B
//   Bs: 192 rows (3 taps x 64 co) x 128B (64 ci fp16)   = 24576 B
#define XS_BYTES (324 * 128)
#define SMEM_BYTES (2 * XS_BYTES + 192 * 128)

__global__ __launch_bounds__(256, 2)
void conv_mma_kernel(const float* __restrict__ x,
                     const float* __restrict__ conv_b,
                     float* __restrict__ out) {
    extern __shared__ char sm[];
    char* xhb = sm;
    char* xlb = sm + XS_BYTES;
    char* bsb = sm + 2 * XS_BYTES;

    int w0 = blockIdx.x * 16, h0 = blockIdx.y * 16, n = blockIdx.z;
    int tid = threadIdx.x, warp = tid >> 5, lane = tid & 31;

    // --- stage x tile (18x18 halo, 64 ci), fp16 hi/lo split, swizzled -------
    const float* xn = x + (size_t)n * C_IN * HH * WW;
    for (int i = tid; i < 18 * 18 * C_IN; i += 256) {
        int ci = i / 324;
        int pos = i - ci * 324;
        int r = pos / 18, c = pos - r * 18;
        int gh = h0 - 1 + r, gw = w0 - 1 + c;
        float v = 0.f;
        if ((unsigned)gh < (unsigned)HH && (unsigned)gw < (unsigned)WW)
            v = xn[ci * (HH * WW) + gh * WW + gw];
        __half hi = __float2half_rn(v);
        __half lo = __float2half_rn(v - __half2float(hi));
        int off = pos * 128 + (((ci >> 3) ^ (pos & 7)) << 4) + ((ci & 7) << 1);
        *(__half*)(xhb + off) = hi;
        *(__half*)(xlb + off) = lo;
    }

    float acc[2][8][4];
    #pragma unroll
    for (int mf = 0; mf < 2; mf++)
        #pragma unroll
        for (int nf = 0; nf < 8; nf++)
            #pragma unroll
            for (int r = 0; r < 4; r++) acc[mf][nf][r] = 0.f;

    // ldmatrix lane geometry (identical to validated round-4 mapping)
    int arow = lane & 15;                        // A: w_local row
    int acb  = lane >> 4;                        // A: k chunk (0/1)
    int brow = (lane & 7) + ((lane >> 4) << 3);  // B: co row within 16
    int bcb  = (lane >> 3) & 1;                  // B: k chunk (0/1)
    int br7  = brow & 7;

    u32 xh_s = su32(xhb), xl_s = su32(xlb), bs_s = su32(bsb);

    const __half* whn = g_wh + (size_t)n * 9 * C_OUT * C_IN;

    for (int g = 0; g < 3; g++) {                // g == kh
        __syncthreads();
        // load B group: taps {g*3..g*3+2}, swizzled rows of 128B
        for (int i = tid; i < 1536; i += 256) {
            int tloc = i >> 9;
            int rr = i & 511;
            int co = rr >> 3, q = rr & 7;
            uint4 v = *(const uint4*)(whn + ((size_t)((g * 3 + tloc) * C_OUT + co)) * C_IN + q * 8);
            int row = tloc * C_OUT + co;
            *(uint4*)(bsb + row * 128 + ((q ^ (co & 7)) << 4)) = v;
        }
        __syncthreads();

        #pragma unroll
        for (int tl = 0; tl < 3; tl++) {         // tl == kw
            int rowA0 = ((2 * warp + 0 + g) * 18 + arow + tl);
            int rowA1 = rowA0 + 18;
            u32 rbA0 = (u32)rowA0 * 128, rA0_7 = rowA0 & 7;
            u32 rbA1 = (u32)rowA1 * 128, rA1_7 = rowA1 & 7;
            #pragma unroll
            for (int kc = 0; kc < 4; kc++) {
                int chA = acb + 2 * kc;
                u32 a0 = rbA0 + (u32)((chA ^ rA0_7) << 4);
                u32 a1 = rbA1 + (u32)((chA ^ rA1_7) << 4);
                u32 ah0[4], ah1[4], al0[4], al1[4];
                LDSM4(ah0, xh_s + a0);
                LDSM4(ah1, xh_s + a1);
                LDSM4(al0, xl_s + a0);
                LDSM4(al1, xl_s + a1);
                u32 bh[16];
                u32 cB = (u32)(((bcb + 2 * kc) ^ br7) << 4);
                #pragma unroll
                for (int p = 0; p < 4; p++) {
                    u32 rowB = (u32)(tl * C_OUT + brow + p * 16) * 128;
                    LDSM4(&bh[4 * p], bs_s + rowB + cB);
                }
                #pragma unroll
                for (int nf = 0; nf < 8; nf++) {
                    int bi = (nf >> 1) * 4 + (nf & 1) * 2;
                    MMA_FP16(acc[0][nf], ah0, bh[bi], bh[bi + 1]);
                    MMA_FP16(acc[1][nf], ah1, bh[bi], bh[bi + 1]);
                }
                #pragma unroll
                for (int nf = 0; nf < 8; nf++) {
                    int bi = (nf >> 1) * 4 + (nf & 1) * 2;
                    MMA_FP16(acc[0][nf], al0, bh[bi], bh[bi + 1]);
                    MMA_FP16(acc[1][nf], al1, bh[bi], bh[bi + 1]);
                }
            }
        }
    }

    // --- epilogue: C rows = w_local, cols = co; add bias ---------------------
    int gg = lane >> 2, tig = lane & 3;
    #pragma unroll
    for (int mf = 0; mf < 2; mf++) {
        int h = h0 + 2 * warp + mf;
        #pragma unroll
        for (int nf = 0; nf < 8; nf++) {
            int co = nf * 8 + tig * 2;
            float b0 = conv_b[co], b1 = conv_b[co + 1];
            size_t base = ((size_t)(n * C_OUT + co) * HH + h) * WW + w0;
            out[base + gg]                 = acc[mf][nf][0] + b0;
            out[base + HH * WW + gg]       = acc[mf][nf][1] + b1;
            out[base + gg + 8]             = acc[mf][nf][2] + b0;
            out[base + HH * WW + gg + 8]   = acc[mf][nf][3] + b1;
        }
    }
}

// ---------------- launch -----------------------------------------------------
extern "C" void kernel_launch(void* const* d_in, const int* in_sizes, int n_in,
                              void* d_out, int out_size) {
    const float* x      = (const float*)d_in[0];
    const float* weight = (const float*)d_in[1];
    const float* conv_w = (const float*)d_in[2];
    const float* conv_b = (const float*)d_in[3];
    const float* net0_w = (const float*)d_in[4];
    const float* net0_b = (const float*)d_in[5];
    const float* net1_w = (const float*)d_in[6];
    const float* net1_b = (const float*)d_in[7];
    const float* net2_w = (const float*)d_in[8];
    const float* net2_b = (const float*)d_in[9];
    float* out = (float*)d_out;

    static int smem_set = 0;
    if (!smem_set) {
        cudaFuncSetAttribute(conv_mma_kernel,
                             cudaFuncAttributeMaxDynamicSharedMemorySize, SMEM_BYTES);
        smem_set = 1;
    }

    zero_sums_kernel<<<1, 512>>>();
    class_sums_kernel<<<256, 256>>>(x);
    logits_softmax_kernel<<<1, 32>>>(net0_w, net0_b, net1_w, net1_b, net2_w, net2_b);
    agg_weights_kernel<<<(NN * 9 * C_OUT * C_IN + 255) / 256, 256>>>(weight, conv_w);
    conv_mma_kernel<<<dim3(WW / 16, HH / 16, NN), 256, SMEM_BYTES>>>(x, conv_b, out);
}

// round 7
// speedup vs baseline: 4.3480x; 1.2956x over previous
#include <cuda_runtime.h>
#include <cuda_fp16.h>
#include <math.h>

#define NN 8
#define C_IN 64
#define C_OUT 64
#define HH 128
#define WW 128
#define KK 4

typedef unsigned int u32;

// ---------------- scratch (device globals; no allocations allowed) ----------
__device__ float g_sums[NN][45];                 // zero at load; re-zeroed each run
__device__ float g_att[NN][KK];
__device__ __half g_wh[NN * 9 * C_OUT * C_IN];   // fused weight fp16, [n][tap][co][ci]

// ---------------- kernel 1: 45 class sums (quarter-channel warps) -----------
__global__ void class_sums_kernel(const float* __restrict__ x) {
    int gwarp = (blockIdx.x * blockDim.x + threadIdx.x) >> 5;   // 0..2047
    int lane = threadIdx.x & 31;
    int ch = gwarp >> 2, q = gwarp & 3;
    int n = ch >> 6, c = ch & 63;
    const float* p = x + (size_t)(n * C_IN + c) * (HH * WW);
    const float* pr = p + q * 32 * WW;

    float T = 0.f;
    #pragma unroll 4
    for (int i = lane; i < 32 * WW; i += 32) T += pr[i];
    float R0 = 0.f, RL = 0.f;
    if (q == 0) for (int i = lane; i < WW; i += 32) R0 += p[i];
    if (q == 3) for (int i = lane; i < WW; i += 32) RL += p[(HH - 1) * WW + i];
    int h = q * 32 + lane;
    float C0 = p[h * WW], CL = p[h * WW + WW - 1];

    #pragma unroll
    for (int o = 16; o; o >>= 1) {
        T  += __shfl_xor_sync(0xffffffffu, T, o);
        R0 += __shfl_xor_sync(0xffffffffu, R0, o);
        RL += __shfl_xor_sync(0xffffffffu, RL, o);
        C0 += __shfl_xor_sync(0xffffffffu, C0, o);
        CL += __shfl_xor_sync(0xffffffffu, CL, o);
    }
    float c00 = (q == 0) ? p[0] : 0.f;
    float c0L = (q == 0) ? p[WW - 1] : 0.f;
    float cL0 = (q == 3) ? p[(HH - 1) * WW] : 0.f;
    float cLL = (q == 3) ? p[HH * WW - 1] : 0.f;
    float S[9];
    S[0] = c00;  S[2] = c0L;
    S[1] = R0 - c00 - c0L;
    S[6] = cL0;  S[8] = cLL;
    S[7] = RL - cL0 - cLL;
    S[3] = C0 - c00 - cL0;
    S[5] = CL - c0L - cLL;
    S[4] = T - R0 - RL - S[3] - S[5];
    int cd = (c == 0) ? 0 : (c == 1) ? 1 : (c == C_IN - 2) ? 3 : (c == C_IN - 1) ? 4 : 2;
    if (lane < 9) atomicAdd(&g_sums[n][cd * 9 + lane], S[lane]);
}

// ---------------- kernel 2: logits + softmax; re-zero g_sums after use ------
__global__ void logits_softmax_kernel(const float* __restrict__ net0_w,
                                      const float* __restrict__ net0_b,
                                      const float* __restrict__ net1_w,
                                      const float* __restrict__ net1_b,
                                      const float* __restrict__ net2_w,
                                      const float* __restrict__ net2_b) {
    __shared__ float lg[NN][KK];
    int t = threadIdx.x;
    if (t < NN * KK) {
        int n = t / KK, k = t % KK;
        float S[5][3][3];
        #pragma unroll
        for (int i = 0; i < 45; i++) ((float*)S)[i] = g_sums[n][i];
        float Stot = 0.f;
        #pragma unroll
        for (int i = 0; i < 45; i++) Stot += ((float*)S)[i];

        const float mh[3][3]  = {{0,1,1},{1,1,1},{1,1,0}};
        const float m1d[3][5] = {{0,1,1,1,1},{1,1,1,1,1},{1,1,1,1,0}};
        const float m2d[5][5] = {{0,0,1,1,1},{0,1,1,1,1},{1,1,1,1,1},{1,1,1,1,0},{1,1,1,0,0}};
        const float invV = 1.0f / (float)(C_IN * HH * WW);

        float acc = net0_b[k] + net1_b[k] + net2_b[k] + net0_w[k] * Stot * invV;

        float s1 = 0.f;
        for (int td = 0; td < 3; td++) {
            float B[3][3];
            for (int ch = 0; ch < 3; ch++)
                for (int cw = 0; cw < 3; cw++) {
                    float v = 0.f;
                    for (int cd = 0; cd < 5; cd++) v += m1d[td][cd] * S[cd][ch][cw];
                    B[ch][cw] = v;
                }
            for (int th = 0; th < 3; th++)
                for (int tw = 0; tw < 3; tw++) {
                    float box = 0.f;
                    for (int ch = 0; ch < 3; ch++)
                        for (int cw = 0; cw < 3; cw++)
                            box += mh[th][ch] * mh[tw][cw] * B[ch][cw];
                    s1 += net1_w[k * 27 + td * 9 + th * 3 + tw] * box;
                }
        }
        float s2 = 0.f;
        for (int td = 0; td < 5; td++) {
            float B[3][3];
            for (int ch = 0; ch < 3; ch++)
                for (int cw = 0; cw < 3; cw++) {
                    float v = 0.f;
                    for (int cd = 0; cd < 5; cd++) v += m2d[td][cd] * S[cd][ch][cw];
                    B[ch][cw] = v;
                }
            for (int th = 0; th < 3; th++)
                for (int tw = 0; tw < 3; tw++) {
                    float box = 0.f;
                    for (int ch = 0; ch < 3; ch++)
                        for (int cw = 0; cw < 3; cw++)
                            box += mh[th][ch] * mh[tw][cw] * B[ch][cw];
                    s2 += net2_w[k * 45 + td * 9 + th * 3 + tw] * box;
                }
        }
        acc += (s1 + s2) * invV;
        lg[n][k] = acc;
    }
    __syncthreads();
    // restore g_sums = 0 for the next run (deterministic invariant)
    for (int i = t; i < NN * 45; i += 32) ((float*)g_sums)[i] = 0.0f;
    if (t < NN * KK) {
        int n = t / KK, k = t % KK;
        float m = lg[n][0];
        #pragma unroll
        for (int j = 1; j < KK; j++) m = fmaxf(m, lg[n][j]);
        float sum = 0.f;
        #pragma unroll
        for (int j = 0; j < KK; j++) sum += expf(lg[n][j] - m);
        g_att[n][k] = expf(lg[n][k] - m) / sum;
    }
}

// ---------------- kernel 3: fused weight -> fp16 [n][tap][co][ci] -----------
// Coalesced read of [co][ci][t] per co-block of 8, smem transpose, coalesced
// fp16 write in [t][co][ci].
__global__ __launch_bounds__(256)
void agg_weights_kernel(const float* __restrict__ weight,
                        const float* __restrict__ conv_w) {
    __shared__ float s[8 * 576];
    int n = blockIdx.x >> 3;
    int cob = blockIdx.x & 7;                    // block of 8 co
    int tid = threadIdx.x;
    float a0 = g_att[n][0], a1 = g_att[n][1], a2 = g_att[n][2], a3 = g_att[n][3];
    const int PER_K = C_OUT * C_IN * 9;
    int base = cob * 8 * 576;
    #pragma unroll
    for (int i = tid; i < 4608; i += 256) {
        float v = conv_w[base + i]
                + a0 * weight[0 * PER_K + base + i]
                + a1 * weight[1 * PER_K + base + i]
                + a2 * weight[2 * PER_K + base + i]
                + a3 * weight[3 * PER_K + base + i];
        s[i] = v;
    }
    __syncthreads();
    #pragma unroll
    for (int i = tid; i < 4608; i += 256) {
        int t = i / 512;
        int r = i - t * 512;
        int j = r >> 6, ci = r & 63;
        g_wh[(((size_t)n * 9 + t) * C_OUT + cob * 8 + j) * C_IN + ci] =
            __float2half_rn(s[(j * 64 + ci) * 9 + t]);
    }
}

// ---------------- kernel 4: tensor-core implicit-GEMM conv (fp16 1-prod) ----
__device__ __forceinline__ u32 su32(const void* p) {
    return (u32)__cvta_generic_to_shared(p);
}

#define LDSM4(R, ADDR)                                                         \
    asm volatile("ldmatrix.sync.aligned.m8n8.x4.shared.b16 {%0,%1,%2,%3}, [%4];" \
                 : "=r"((R)[0]), "=r"((R)[1]), "=r"((R)[2]), "=r"((R)[3])      \
                 : "r"(ADDR))

#define MMA_FP16(C, A, B0, B1)                                                 \
    asm volatile("mma.sync.aligned.m16n8k16.row.col.f32.f16.f16.f32 "         \
                 "{%0,%1,%2,%3}, {%4,%5,%6,%7}, {%8,%9}, {%0,%1,%2,%3};"      \
                 : "+f"((C)[0]), "+f"((C)[1]), "+f"((C)[2]), "+f"((C)[3])     \
                 : "r"((A)[0]), "r"((A)[1]), "r"((A)[2]), "r"((A)[3]),        \
                   "r"(B0), "r"(B1))

// smem: xh 324 rows x 128B (swizzled), Bs 192 rows x 128B
#define XS_BYTES (324 * 128)
#define SMEM_BYTES (XS_BYTES + 192 * 128)

__global__ __launch_bounds__(256, 2)
void conv_mma_kernel(const float* __restrict__ x,
                     const float* __restrict__ conv_b,
                     float* __restrict__ out) {
    extern __shared__ char sm[];
    char* xhb = sm;
    char* bsb = sm + XS_BYTES;

    int w0 = blockIdx.x * 16, h0 = blockIdx.y * 16, n = blockIdx.z;
    int tid = threadIdx.x, warp = tid >> 5, lane = tid & 31;

    // --- stage x tile (18x18 halo, 64 ci) as fp16, swizzled -------------------
    const float* xn = x + (size_t)n * C_IN * HH * WW;
    for (int i = tid; i < 18 * 18 * C_IN; i += 256) {
        int ci = i / 324;
        int pos = i - ci * 324;
        int r = pos / 18, c = pos - r * 18;
        int gh = h0 - 1 + r, gw = w0 - 1 + c;
        float v = 0.f;
        if ((unsigned)gh < (unsigned)HH && (unsigned)gw < (unsigned)WW)
            v = xn[ci * (HH * WW) + gh * WW + gw];
        int off = pos * 128 + (((ci >> 3) ^ (pos & 7)) << 4) + ((ci & 7) << 1);
        *(__half*)(xhb + off) = __float2half_rn(v);
    }

    float acc[2][8][4];
    #pragma unroll
    for (int mf = 0; mf < 2; mf++)
        #pragma unroll
        for (int nf = 0; nf < 8; nf++)
            #pragma unroll
            for (int r = 0; r < 4; r++) acc[mf][nf][r] = 0.f;

    // ldmatrix lane geometry (validated mapping)
    int arow = lane & 15;                        // A: w_local row
    int acb  = lane >> 4;                        // A: k chunk (0/1)
    int brow = (lane & 7) + ((lane >> 4) << 3);  // B: co row within 16
    int bcb  = (lane >> 3) & 1;                  // B: k chunk (0/1)
    int br7  = brow & 7;

    u32 xh_s = su32(xhb), bs_s = su32(bsb);
    const __half* whn = g_wh + (size_t)n * 9 * C_OUT * C_IN;

    for (int g = 0; g < 3; g++) {                // g == kh
        __syncthreads();
        for (int i = tid; i < 1536; i += 256) {
            int tloc = i >> 9;
            int rr = i & 511;
            int co = rr >> 3, q = rr & 7;
            uint4 v = *(const uint4*)(whn + ((size_t)((g * 3 + tloc) * C_OUT + co)) * C_IN + q * 8);
            int row = tloc * C_OUT + co;
            *(uint4*)(bsb + row * 128 + ((q ^ (co & 7)) << 4)) = v;
        }
        __syncthreads();

        #pragma unroll
        for (int tl = 0; tl < 3; tl++) {         // tl == kw
            int rowA0 = ((2 * warp + 0 + g) * 18 + arow + tl);
            int rowA1 = rowA0 + 18;
            u32 rbA0 = (u32)rowA0 * 128, rA0_7 = rowA0 & 7;
            u32 rbA1 = (u32)rowA1 * 128, rA1_7 = rowA1 & 7;
            #pragma unroll
            for (int kc = 0; kc < 4; kc++) {
                int chA = acb + 2 * kc;
                u32 a0 = rbA0 + (u32)((chA ^ rA0_7) << 4);
                u32 a1 = rbA1 + (u32)((chA ^ rA1_7) << 4);
                u32 ah0[4], ah1[4];
                LDSM4(ah0, xh_s + a0);
                LDSM4(ah1, xh_s + a1);
                u32 bh[16];
                u32 cB = (u32)(((bcb + 2 * kc) ^ br7) << 4);
                #pragma unroll
                for (int p = 0; p < 4; p++) {
                    u32 rowB = (u32)(tl * C_OUT + brow + p * 16) * 128;
                    LDSM4(&bh[4 * p], bs_s + rowB + cB);
                }
                #pragma unroll
                for (int nf = 0; nf < 8; nf++) {
                    int bi = (nf >> 1) * 4 + (nf & 1) * 2;
                    MMA_FP16(acc[0][nf], ah0, bh[bi], bh[bi + 1]);
                    MMA_FP16(acc[1][nf], ah1, bh[bi], bh[bi + 1]);
                }
            }
        }
    }

    // --- epilogue: C rows = w_local, cols = co; add bias ---------------------
    int gg = lane >> 2, tig = lane & 3;
    #pragma unroll
    for (int mf = 0; mf < 2; mf++) {
        int h = h0 + 2 * warp + mf;
        #pragma unroll
        for (int nf = 0; nf < 8; nf++) {
            int co = nf * 8 + tig * 2;
            float b0 = conv_b[co], b1 = conv_b[co + 1];
            size_t base = ((size_t)(n * C_OUT + co) * HH + h) * WW + w0;
            out[base + gg]                 = acc[mf][nf][0] + b0;
            out[base + HH * WW + gg]       = acc[mf][nf][1] + b1;
            out[base + gg + 8]             = acc[mf][nf][2] + b0;
            out[base + HH * WW + gg + 8]   = acc[mf][nf][3] + b1;
        }
    }
}

// ---------------- launch -----------------------------------------------------
extern "C" void kernel_launch(void* const* d_in, const int* in_sizes, int n_in,
                              void* d_out, int out_size) {
    const float* x      = (const float*)d_in[0];
    const float* weight = (const float*)d_in[1];
    const float* conv_w = (const float*)d_in[2];
    const float* conv_b = (const float*)d_in[3];
    const float* net0_w = (const float*)d_in[4];
    const float* net0_b = (const float*)d_in[5];
    const float* net1_w = (const float*)d_in[6];
    const float* net1_b = (const float*)d_in[7];
    const float* net2_w = (const float*)d_in[8];
    const float* net2_b = (const float*)d_in[9];
    float* out = (float*)d_out;

    static int smem_set = 0;
    if (!smem_set) {
        cudaFuncSetAttribute(conv_mma_kernel,
                             cudaFuncAttributeMaxDynamicSharedMemorySize, SMEM_BYTES);
        smem_set = 1;
    }

    class_sums_kernel<<<256, 256>>>(x);
    logits_softmax_kernel<<<1, 32>>>(net0_w, net0_b, net1_w, net1_b, net2_w, net2_b);
    agg_weights_kernel<<<NN * 8, 256>>>(weight, conv_w);
    conv_mma_kernel<<<dim3(WW / 16, HH / 16, NN), 256, SMEM_BYTES>>>(x, conv_b, out);
}

// round 8
// speedup vs baseline: 4.3623x; 1.0033x over previous
#include <cuda_runtime.h>
#include <cuda_fp16.h>
#include <math.h>

#define NN 8
#define C_IN 64
#define C_OUT 64
#define HH 128
#define WW 128
#define KK 4

typedef unsigned int u32;

// ---------------- scratch (device globals; no allocations allowed) ----------
__device__ float g_sums[NN][45];                 // zero at load; re-zeroed each run
__device__ float g_att[NN][KK];
__device__ __half g_wh[NN * 9 * C_OUT * C_IN];   // fused weight fp16, [n][tap][co][ci]

// ---------------- kernel 1: 45 class sums (quarter-channel warps) -----------
__global__ void class_sums_kernel(const float* __restrict__ x) {
    int gwarp = (blockIdx.x * blockDim.x + threadIdx.x) >> 5;   // 0..2047
    int lane = threadIdx.x & 31;
    int ch = gwarp >> 2, q = gwarp & 3;
    int n = ch >> 6, c = ch & 63;
    const float* p = x + (size_t)(n * C_IN + c) * (HH * WW);
    const float* pr = p + q * 32 * WW;

    float T = 0.f;
    #pragma unroll 4
    for (int i = lane; i < 32 * WW; i += 32) T += pr[i];
    float R0 = 0.f, RL = 0.f;
    if (q == 0) for (int i = lane; i < WW; i += 32) R0 += p[i];
    if (q == 3) for (int i = lane; i < WW; i += 32) RL += p[(HH - 1) * WW + i];
    int h = q * 32 + lane;
    float C0 = p[h * WW], CL = p[h * WW + WW - 1];

    #pragma unroll
    for (int o = 16; o; o >>= 1) {
        T  += __shfl_xor_sync(0xffffffffu, T, o);
        R0 += __shfl_xor_sync(0xffffffffu, R0, o);
        RL += __shfl_xor_sync(0xffffffffu, RL, o);
        C0 += __shfl_xor_sync(0xffffffffu, C0, o);
        CL += __shfl_xor_sync(0xffffffffu, CL, o);
    }
    float c00 = (q == 0) ? p[0] : 0.f;
    float c0L = (q == 0) ? p[WW - 1] : 0.f;
    float cL0 = (q == 3) ? p[(HH - 1) * WW] : 0.f;
    float cLL = (q == 3) ? p[HH * WW - 1] : 0.f;
    float S[9];
    S[0] = c00;  S[2] = c0L;
    S[1] = R0 - c00 - c0L;
    S[6] = cL0;  S[8] = cLL;
    S[7] = RL - cL0 - cLL;
    S[3] = C0 - c00 - cL0;
    S[5] = CL - c0L - cLL;
    S[4] = T - R0 - RL - S[3] - S[5];
    int cd = (c == 0) ? 0 : (c == 1) ? 1 : (c == C_IN - 2) ? 3 : (c == C_IN - 1) ? 4 : 2;
    if (lane < 9) atomicAdd(&g_sums[n][cd * 9 + lane], S[lane]);
}

// ---------------- kernel 2: logits + softmax; re-zero g_sums after use ------
__global__ void logits_softmax_kernel(const float* __restrict__ net0_w,
                                      const float* __restrict__ net0_b,
                                      const float* __restrict__ net1_w,
                                      const float* __restrict__ net1_b,
                                      const float* __restrict__ net2_w,
                                      const float* __restrict__ net2_b) {
    __shared__ float lg[NN][KK];
    int t = threadIdx.x;
    if (t < NN * KK) {
        int n = t / KK, k = t % KK;
        float S[5][3][3];
        #pragma unroll
        for (int i = 0; i < 45; i++) ((float*)S)[i] = g_sums[n][i];
        float Stot = 0.f;
        #pragma unroll
        for (int i = 0; i < 45; i++) Stot += ((float*)S)[i];

        const float mh[3][3]  = {{0,1,1},{1,1,1},{1,1,0}};
        const float m1d[3][5] = {{0,1,1,1,1},{1,1,1,1,1},{1,1,1,1,0}};
        const float m2d[5][5] = {{0,0,1,1,1},{0,1,1,1,1},{1,1,1,1,1},{1,1,1,1,0},{1,1,1,0,0}};
        const float invV = 1.0f / (float)(C_IN * HH * WW);

        float acc = net0_b[k] + net1_b[k] + net2_b[k] + net0_w[k] * Stot * invV;

        float s1 = 0.f;
        for (int td = 0; td < 3; td++) {
            float B[3][3];
            for (int ch = 0; ch < 3; ch++)
                for (int cw = 0; cw < 3; cw++) {
                    float v = 0.f;
                    for (int cd = 0; cd < 5; cd++) v += m1d[td][cd] * S[cd][ch][cw];
                    B[ch][cw] = v;
                }
            for (int th = 0; th < 3; th++)
                for (int tw = 0; tw < 3; tw++) {
                    float box = 0.f;
                    for (int ch = 0; ch < 3; ch++)
                        for (int cw = 0; cw < 3; cw++)
                            box += mh[th][ch] * mh[tw][cw] * B[ch][cw];
                    s1 += net1_w[k * 27 + td * 9 + th * 3 + tw] * box;
                }
        }
        float s2 = 0.f;
        for (int td = 0; td < 5; td++) {
            float B[3][3];
            for (int ch = 0; ch < 3; ch++)
                for (int cw = 0; cw < 3; cw++) {
                    float v = 0.f;
                    for (int cd = 0; cd < 5; cd++) v += m2d[td][cd] * S[cd][ch][cw];
                    B[ch][cw] = v;
                }
            for (int th = 0; th < 3; th++)
                for (int tw = 0; tw < 3; tw++) {
                    float box = 0.f;
                    for (int ch = 0; ch < 3; ch++)
                        for (int cw = 0; cw < 3; cw++)
                            box += mh[th][ch] * mh[tw][cw] * B[ch][cw];
                    s2 += net2_w[k * 45 + td * 9 + th * 3 + tw] * box;
                }
        }
        acc += (s1 + s2) * invV;
        lg[n][k] = acc;
    }
    __syncthreads();
    // restore g_sums = 0 for the next run (deterministic invariant)
    for (int i = t; i < NN * 45; i += 32) ((float*)g_sums)[i] = 0.0f;
    if (t < NN * KK) {
        int n = t / KK, k = t % KK;
        float m = lg[n][0];
        #pragma unroll
        for (int j = 1; j < KK; j++) m = fmaxf(m, lg[n][j]);
        float sum = 0.f;
        #pragma unroll
        for (int j = 0; j < KK; j++) sum += expf(lg[n][j] - m);
        g_att[n][k] = expf(lg[n][k] - m) / sum;
    }
}

// ---------------- kernel 3: fused weight -> fp16 [n][tap][co][ci] -----------
__global__ __launch_bounds__(256)
void agg_weights_kernel(const float* __restrict__ weight,
                        const float* __restrict__ conv_w) {
    __shared__ float s[8 * 576];
    int n = blockIdx.x >> 3;
    int cob = blockIdx.x & 7;                    // block of 8 co
    int tid = threadIdx.x;
    float a0 = g_att[n][0], a1 = g_att[n][1], a2 = g_att[n][2], a3 = g_att[n][3];
    const int PER_K = C_OUT * C_IN * 9;
    int base = cob * 8 * 576;
    #pragma unroll
    for (int i = tid; i < 4608; i += 256) {
        float v = conv_w[base + i]
                + a0 * weight[0 * PER_K + base + i]
                + a1 * weight[1 * PER_K + base + i]
                + a2 * weight[2 * PER_K + base + i]
                + a3 * weight[3 * PER_K + base + i];
        s[i] = v;
    }
    __syncthreads();
    #pragma unroll
    for (int i = tid; i < 4608; i += 256) {
        int t = i / 512;
        int r = i - t * 512;
        int j = r >> 6, ci = r & 63;
        g_wh[(((size_t)n * 9 + t) * C_OUT + cob * 8 + j) * C_IN + ci] =
            __float2half_rn(s[(j * 64 + ci) * 9 + t]);
    }
}

// ---------------- kernel 4: tensor-core implicit-GEMM conv ------------------
__device__ __forceinline__ u32 su32(const void* p) {
    return (u32)__cvta_generic_to_shared(p);
}

#define LDSM4(R, ADDR)                                                         \
    asm volatile("ldmatrix.sync.aligned.m8n8.x4.shared.b16 {%0,%1,%2,%3}, [%4];" \
                 : "=r"((R)[0]), "=r"((R)[1]), "=r"((R)[2]), "=r"((R)[3])      \
                 : "r"(ADDR))

#define MMA_FP16(C, A, B0, B1)                                                 \
    asm volatile("mma.sync.aligned.m16n8k16.row.col.f32.f16.f16.f32 "         \
                 "{%0,%1,%2,%3}, {%4,%5,%6,%7}, {%8,%9}, {%0,%1,%2,%3};"      \
                 : "+f"((C)[0]), "+f"((C)[1]), "+f"((C)[2]), "+f"((C)[3])     \
                 : "r"((A)[0]), "r"((A)[1]), "r"((A)[2]), "r"((A)[3]),        \
                   "r"(B0), "r"(B1))

// Block tile: 8h x 16w x 64co. Warp = (h-pair, co-half): acc 32 regs/thread.
// smem: xh 180 rows (10x18 halo) x 128B swizzled = 23040B; Bs 192x128B = 24576B
#define XS_BYTES (180 * 128)
#define SMEM_BYTES (XS_BYTES + 192 * 128)

__global__ __launch_bounds__(256, 3)
void conv_mma_kernel(const float* __restrict__ x,
                     const float* __restrict__ conv_b,
                     float* __restrict__ out) {
    extern __shared__ char sm[];
    char* xhb = sm;
    char* bsb = sm + XS_BYTES;

    int w0 = blockIdx.x * 16, h0 = blockIdx.y * 8, n = blockIdx.z;
    int tid = threadIdx.x, warp = tid >> 5, lane = tid & 31;
    int hp  = warp & 3;                          // h-pair 0..3
    int coh = (warp >> 2) * 32;                  // co half offset

    // --- stage x tile (10x18 halo, 64 ci) as fp16, swizzled -------------------
    const float* xn = x + (size_t)n * C_IN * HH * WW;
    for (int i = tid; i < 10 * 18 * C_IN; i += 256) {
        int ci = i / 180;
        int pos = i - ci * 180;
        int r = pos / 18, c = pos - r * 18;
        int gh = h0 - 1 + r, gw = w0 - 1 + c;
        float v = 0.f;
        if ((unsigned)gh < (unsigned)HH && (unsigned)gw < (unsigned)WW)
            v = xn[ci * (HH * WW) + gh * WW + gw];
        int off = pos * 128 + (((ci >> 3) ^ (pos & 7)) << 4) + ((ci & 7) << 1);
        *(__half*)(xhb + off) = __float2half_rn(v);
    }

    float acc[2][4][4];
    #pragma unroll
    for (int mf = 0; mf < 2; mf++)
        #pragma unroll
        for (int nf = 0; nf < 4; nf++)
            #pragma unroll
            for (int r = 0; r < 4; r++) acc[mf][nf][r] = 0.f;

    // ldmatrix lane geometry (validated mapping)
    int arow = lane & 15;                        // A: w_local row
    int acb  = lane >> 4;                        // A: k chunk (0/1)
    int brow = (lane & 7) + ((lane >> 4) << 3);  // B: co row within 16
    int bcb  = (lane >> 3) & 1;                  // B: k chunk (0/1)
    int br7  = brow & 7;

    u32 xh_s = su32(xhb), bs_s = su32(bsb);
    const __half* whn = g_wh + (size_t)n * 9 * C_OUT * C_IN;

    for (int g = 0; g < 3; g++) {                // g == kh
        __syncthreads();
        for (int i = tid; i < 1536; i += 256) {
            int tloc = i >> 9;
            int rr = i & 511;
            int co = rr >> 3, q = rr & 7;
            uint4 v = *(const uint4*)(whn + ((size_t)((g * 3 + tloc) * C_OUT + co)) * C_IN + q * 8);
            int row = tloc * C_OUT + co;
            *(uint4*)(bsb + row * 128 + ((q ^ (co & 7)) << 4)) = v;
        }
        __syncthreads();

        #pragma unroll
        for (int tl = 0; tl < 3; tl++) {         // tl == kw
            int rowA0 = (2 * hp + 0 + g) * 18 + arow + tl;
            int rowA1 = rowA0 + 18;
            u32 rbA0 = (u32)rowA0 * 128, rA0_7 = rowA0 & 7;
            u32 rbA1 = (u32)rowA1 * 128, rA1_7 = rowA1 & 7;
            #pragma unroll
            for (int kc = 0; kc < 4; kc++) {
                int chA = acb + 2 * kc;
                u32 a0 = rbA0 + (u32)((chA ^ rA0_7) << 4);
                u32 a1 = rbA1 + (u32)((chA ^ rA1_7) << 4);
                u32 ah0[4], ah1[4];
                LDSM4(ah0, xh_s + a0);
                LDSM4(ah1, xh_s + a1);
                u32 bh[8];
                u32 cB = (u32)(((bcb + 2 * kc) ^ br7) << 4);
                #pragma unroll
                for (int p = 0; p < 2; p++) {
                    u32 rowB = (u32)(tl * C_OUT + coh + brow + p * 16) * 128;
                    LDSM4(&bh[4 * p], bs_s + rowB + cB);
                }
                #pragma unroll
                for (int nf = 0; nf < 4; nf++) {
                    int bi = (nf >> 1) * 4 + (nf & 1) * 2;
                    MMA_FP16(acc[0][nf], ah0, bh[bi], bh[bi + 1]);
                    MMA_FP16(acc[1][nf], ah1, bh[bi], bh[bi + 1]);
                }
            }
        }
    }

    // --- epilogue: add bias, store --------------------------------------------
    int gg = lane >> 2, tig = lane & 3;
    #pragma unroll
    for (int mf = 0; mf < 2; mf++) {
        int h = h0 + 2 * hp + mf;
        #pragma unroll
        for (int nf = 0; nf < 4; nf++) {
            int co = coh + nf * 8 + tig * 2;
            float b0 = conv_b[co], b1 = conv_b[co + 1];
            size_t base = ((size_t)(n * C_OUT + co) * HH + h) * WW + w0;
            out[base + gg]                 = acc[mf][nf][0] + b0;
            out[base + HH * WW + gg]       = acc[mf][nf][1] + b1;
            out[base + gg + 8]             = acc[mf][nf][2] + b0;
            out[base + HH * WW + gg + 8]   = acc[mf][nf][3] + b1;
        }
    }
}

// ---------------- launch -----------------------------------------------------
extern "C" void kernel_launch(void* const* d_in, const int* in_sizes, int n_in,
                              void* d_out, int out_size) {
    const float* x      = (const float*)d_in[0];
    const float* weight = (const float*)d_in[1];
    const float* conv_w = (const float*)d_in[2];
    const float* conv_b = (const float*)d_in[3];
    const float* net0_w = (const float*)d_in[4];
    const float* net0_b = (const float*)d_in[5];
    const float* net1_w = (const float*)d_in[6];
    const float* net1_b = (const float*)d_in[7];
    const float* net2_w = (const float*)d_in[8];
    const float* net2_b = (const float*)d_in[9];
    float* out = (float*)d_out;

    static int smem_set = 0;
    if (!smem_set) {
        cudaFuncSetAttribute(conv_mma_kernel,
                             cudaFuncAttributeMaxDynamicSharedMemorySize, SMEM_BYTES);
        smem_set = 1;
    }

    class_sums_kernel<<<256, 256>>>(x);
    logits_softmax_kernel<<<1, 32>>>(net0_w, net0_b, net1_w, net1_b, net2_w, net2_b);
    agg_weights_kernel<<<NN * 8, 256>>>(weight, conv_w);
    conv_mma_kernel<<<dim3(WW / 16, HH / 8, NN), 256, SMEM_BYTES>>>(x, conv_b, out);
}

// round 10
// speedup vs baseline: 5.5487x; 1.2720x over previous
#include <cuda_runtime.h>
#include <cuda_fp16.h>
#include <math.h>

#define NN 8
#define C_IN 64
#define C_OUT 64
#define HH 128
#define WW 128
#define KK 4

typedef unsigned int u32;

// ---------------- scratch (device globals; no allocations allowed) ----------
__device__ float g_sums[NN][45];                 // zero at load; re-zeroed each run
__device__ float g_att[NN][KK];
__device__ __half g_wh[NN * 9 * C_OUT * C_IN];   // fused weight fp16, [n][tap][co][ci]

// ---------------- kernel 1: 45 class sums (quarter-channel warps) -----------
__global__ void class_sums_kernel(const float* __restrict__ x) {
    int gwarp = (blockIdx.x * blockDim.x + threadIdx.x) >> 5;   // 0..2047
    int lane = threadIdx.x & 31;
    int ch = gwarp >> 2, q = gwarp & 3;
    int n = ch >> 6, c = ch & 63;
    const float* p = x + (size_t)(n * C_IN + c) * (HH * WW);
    const float* pr = p + q * 32 * WW;

    float T = 0.f;
    #pragma unroll 4
    for (int i = lane; i < 32 * WW; i += 32) T += pr[i];
    float R0 = 0.f, RL = 0.f;
    if (q == 0) for (int i = lane; i < WW; i += 32) R0 += p[i];
    if (q == 3) for (int i = lane; i < WW; i += 32) RL += p[(HH - 1) * WW + i];
    int h = q * 32 + lane;
    float C0 = p[h * WW], CL = p[h * WW + WW - 1];

    #pragma unroll
    for (int o = 16; o; o >>= 1) {
        T  += __shfl_xor_sync(0xffffffffu, T, o);
        R0 += __shfl_xor_sync(0xffffffffu, R0, o);
        RL += __shfl_xor_sync(0xffffffffu, RL, o);
        C0 += __shfl_xor_sync(0xffffffffu, C0, o);
        CL += __shfl_xor_sync(0xffffffffu, CL, o);
    }
    float c00 = (q == 0) ? p[0] : 0.f;
    float c0L = (q == 0) ? p[WW - 1] : 0.f;
    float cL0 = (q == 3) ? p[(HH - 1) * WW] : 0.f;
    float cLL = (q == 3) ? p[HH * WW - 1] : 0.f;
    float S[9];
    S[0] = c00;  S[2] = c0L;
    S[1] = R0 - c00 - c0L;
    S[6] = cL0;  S[8] = cLL;
    S[7] = RL - cL0 - cLL;
    S[3] = C0 - c00 - cL0;
    S[5] = CL - c0L - cLL;
    S[4] = T - R0 - RL - S[3] - S[5];
    int cd = (c == 0) ? 0 : (c == 1) ? 1 : (c == C_IN - 2) ? 3 : (c == C_IN - 1) ? 4 : 2;
    if (lane < 9) atomicAdd(&g_sums[n][cd * 9 + lane], S[lane]);
}

// ---------------- kernel 2: logits + softmax; re-zero g_sums after use ------
__global__ void logits_softmax_kernel(const float* __restrict__ net0_w,
                                      const float* __restrict__ net0_b,
                                      const float* __restrict__ net1_w,
                                      const float* __restrict__ net1_b,
                                      const float* __restrict__ net2_w,
                                      const float* __restrict__ net2_b) {
    __shared__ float lg[NN][KK];
    int t = threadIdx.x;
    if (t < NN * KK) {
        int n = t / KK, k = t % KK;
        float S[5][3][3];
        #pragma unroll
        for (int i = 0; i < 45; i++) ((float*)S)[i] = g_sums[n][i];
        float Stot = 0.f;
        #pragma unroll
        for (int i = 0; i < 45; i++) Stot += ((float*)S)[i];

        const float mh[3][3]  = {{0,1,1},{1,1,1},{1,1,0}};
        const float m1d[3][5] = {{0,1,1,1,1},{1,1,1,1,1},{1,1,1,1,0}};
        const float m2d[5][5] = {{0,0,1,1,1},{0,1,1,1,1},{1,1,1,1,1},{1,1,1,1,0},{1,1,1,0,0}};
        const float invV = 1.0f / (float)(C_IN * HH * WW);

        float acc = net0_b[k] + net1_b[k] + net2_b[k] + net0_w[k] * Stot * invV;

        float s1 = 0.f;
        for (int td = 0; td < 3; td++) {
            float B[3][3];
            for (int ch = 0; ch < 3; ch++)
                for (int cw = 0; cw < 3; cw++) {
                    float v = 0.f;
                    for (int cd = 0; cd < 5; cd++) v += m1d[td][cd] * S[cd][ch][cw];
                    B[ch][cw] = v;
                }
            for (int th = 0; th < 3; th++)
                for (int tw = 0; tw < 3; tw++) {
                    float box = 0.f;
                    for (int ch = 0; ch < 3; ch++)
                        for (int cw = 0; cw < 3; cw++)
                            box += mh[th][ch] * mh[tw][cw] * B[ch][cw];
                    s1 += net1_w[k * 27 + td * 9 + th * 3 + tw] * box;
                }
        }
        float s2 = 0.f;
        for (int td = 0; td < 5; td++) {
            float B[3][3];
            for (int ch = 0; ch < 3; ch++)
                for (int cw = 0; cw < 3; cw++) {
                    float v = 0.f;
                    for (int cd = 0; cd < 5; cd++) v += m2d[td][cd] * S[cd][ch][cw];
                    B[ch][cw] = v;
                }
            for (int th = 0; th < 3; th++)
                for (int tw = 0; tw < 3; tw++) {
                    float box = 0.f;
                    for (int ch = 0; ch < 3; ch++)
                        for (int cw = 0; cw < 3; cw++)
                            box += mh[th][ch] * mh[tw][cw] * B[ch][cw];
                    s2 += net2_w[k * 45 + td * 9 + th * 3 + tw] * box;
                }
        }
        acc += (s1 + s2) * invV;
        lg[n][k] = acc;
    }
    __syncthreads();
    // restore g_sums = 0 for the next run (deterministic invariant)
    for (int i = t; i < NN * 45; i += 32) ((float*)g_sums)[i] = 0.0f;
    if (t < NN * KK) {
        int n = t / KK, k = t % KK;
        float m = lg[n][0];
        #pragma unroll
        for (int j = 1; j < KK; j++) m = fmaxf(m, lg[n][j]);
        float sum = 0.f;
        #pragma unroll
        for (int j = 0; j < KK; j++) sum += expf(lg[n][j] - m);
        g_att[n][k] = expf(lg[n][k] - m) / sum;
    }
}

// ---------------- kernel 3: fused weight -> fp16 [n][tap][co][ci] -----------
__global__ __launch_bounds__(256)
void agg_weights_kernel(const float* __restrict__ weight,
                        const float* __restrict__ conv_w) {
    __shared__ float s[8 * 576];
    int n = blockIdx.x >> 3;
    int cob = blockIdx.x & 7;                    // block of 8 co
    int tid = threadIdx.x;
    float a0 = g_att[n][0], a1 = g_att[n][1], a2 = g_att[n][2], a3 = g_att[n][3];
    const int PER_K = C_OUT * C_IN * 9;
    int base = cob * 8 * 576;
    #pragma unroll
    for (int i = tid; i < 4608; i += 256) {
        float v = conv_w[base + i]
                + a0 * weight[0 * PER_K + base + i]
                + a1 * weight[1 * PER_K + base + i]
                + a2 * weight[2 * PER_K + base + i]
                + a3 * weight[3 * PER_K + base + i];
        s[i] = v;
    }
    __syncthreads();
    #pragma unroll
    for (int i = tid; i < 4608; i += 256) {
        int t = i / 512;
        int r = i - t * 512;
        int j = r >> 6, ci = r & 63;
        g_wh[(((size_t)n * 9 + t) * C_OUT + cob * 8 + j) * C_IN + ci] =
            __float2half_rn(s[(j * 64 + ci) * 9 + t]);
    }
}

// ---------------- kernel 4: tensor-core implicit-GEMM conv ------------------
__device__ __forceinline__ u32 su32(const void* p) {
    return (u32)__cvta_generic_to_shared(p);
}

#define LDSM4(R, ADDR)                                                         \
    asm volatile("ldmatrix.sync.aligned.m8n8.x4.shared.b16 {%0,%1,%2,%3}, [%4];" \
                 : "=r"((R)[0]), "=r"((R)[1]), "=r"((R)[2]), "=r"((R)[3])      \
                 : "r"(ADDR))

#define MMA_FP16(C, A, B0, B1)                                                 \
    asm volatile("mma.sync.aligned.m16n8k16.row.col.f32.f16.f16.f32 "         \
                 "{%0,%1,%2,%3}, {%4,%5,%6,%7}, {%8,%9}, {%0,%1,%2,%3};"      \
                 : "+f"((C)[0]), "+f"((C)[1]), "+f"((C)[2]), "+f"((C)[3])     \
                 : "r"((A)[0]), "r"((A)[1]), "r"((A)[2]), "r"((A)[3]),        \
                   "r"(B0), "r"(B1))

#define CP_ASYNC16(DST, SRC)                                                   \
    asm volatile("cp.async.cg.shared.global [%0], [%1], 16;" :: "r"(DST), "l"(SRC))
#define CP_ASYNC_WAIT()                                                        \
    asm volatile("cp.async.commit_group;\ncp.async.wait_group 0;" ::: "memory")

// Block tile: 8h x 16w x 64co. Warp = (h-pair, co-half): acc 32 regs/thread.
// smem: xh 180 rows (10x18 halo) x 128B swizzled = 23040B
//       Bs  576 rows (9 taps x 64 co) x 128B     = 73728B  (all taps resident)
#define XS_BYTES (180 * 128)
#define SMEM_BYTES (XS_BYTES + 576 * 128)

__global__ __launch_bounds__(256, 2)
void conv_mma_kernel(const float* __restrict__ x,
                     const float* __restrict__ conv_b,
                     float* __restrict__ out) {
    extern __shared__ char sm[];
    char* xhb = sm;
    char* bsb = sm + XS_BYTES;
    u32 xh_s = su32(xhb), bs_s = su32(bsb);

    int w0 = blockIdx.x * 16, h0 = blockIdx.y * 8, n = blockIdx.z;
    int tid = threadIdx.x, warp = tid >> 5, lane = tid & 31;
    int hp  = warp & 3;                          // h-pair 0..3
    int coh = (warp >> 2) * 32;                  // co half offset

    // --- B: all 9 taps via cp.async (16B, swizzled) ---------------------------
    const __half* whn = g_wh + (size_t)n * 9 * C_OUT * C_IN;
    #pragma unroll
    for (int i = tid; i < 4608; i += 256) {
        int tap = i >> 9;
        int r = i & 511;
        int co = r >> 3, q = r & 7;
        u32 dst = bs_s + (u32)(tap * C_OUT + co) * 128 + ((q ^ (co & 7)) << 4);
        CP_ASYNC16(dst, whn + ((size_t)(tap * C_OUT + co)) * C_IN + q * 8);
    }

    // --- x tile: thread per (pos, 8-ci chunk) -> one STS.128 ------------------
    const float* xn = x + (size_t)n * C_IN * HH * WW;
    #pragma unroll
    for (int i = tid; i < 180 * 8; i += 256) {
        int cib = i / 180;                       // 8-ci chunk index 0..7
        int pos = i - cib * 180;
        int r = pos / 18, c = pos - r * 18;
        int gh = h0 - 1 + r, gw = w0 - 1 + c;
        bool valid = (unsigned)gh < (unsigned)HH && (unsigned)gw < (unsigned)WW;
        const float* px = xn + (size_t)cib * 8 * (HH * WW) + gh * WW + gw;
        u32 pk[4];
        #pragma unroll
        for (int j = 0; j < 4; j++) {
            float v0 = valid ? px[(2 * j + 0) * (HH * WW)] : 0.f;
            float v1 = valid ? px[(2 * j + 1) * (HH * WW)] : 0.f;
            __half2 h2 = __floats2half2_rn(v0, v1);
            pk[j] = *(u32*)&h2;
        }
        u32 off = (u32)pos * 128 + ((cib ^ (pos & 7)) << 4);
        asm volatile("st.shared.v4.b32 [%0], {%1,%2,%3,%4};"
                     :: "r"(xh_s + off), "r"(pk[0]), "r"(pk[1]), "r"(pk[2]), "r"(pk[3]));
    }
    CP_ASYNC_WAIT();
    __syncthreads();

    float acc[2][4][4];
    #pragma unroll
    for (int mf = 0; mf < 2; mf++)
        #pragma unroll
        for (int nf = 0; nf < 4; nf++)
            #pragma unroll
            for (int r = 0; r < 4; r++) acc[mf][nf][r] = 0.f;

    // ldmatrix lane geometry (validated mapping)
    int arow = lane & 15;                        // A: w_local row
    int acb  = lane >> 4;                        // A: k chunk (0/1)
    int brow = (lane & 7) + ((lane >> 4) << 3);  // B: co row within 16
    int bcb  = (lane >> 3) & 1;                  // B: k chunk (0/1)
    int br7  = brow & 7;

    // --- barrier-free main loop: 9 taps x 4 kc --------------------------------
    #pragma unroll
    for (int g = 0; g < 3; g++) {                // kh
        #pragma unroll
        for (int tl = 0; tl < 3; tl++) {         // kw
            int rowA0 = (2 * hp + 0 + g) * 18 + arow + tl;
            int rowA1 = rowA0 + 18;
            u32 rbA0 = (u32)rowA0 * 128, rA0_7 = rowA0 & 7;
            u32 rbA1 = (u32)rowA1 * 128, rA1_7 = rowA1 & 7;
            u32 tapbase = (u32)((g * 3 + tl) * C_OUT + coh);
            #pragma unroll
            for (int kc = 0; kc < 4; kc++) {
                int chA = acb + 2 * kc;
                u32 a0 = rbA0 + (u32)((chA ^ rA0_7) << 4);
                u32 a1 = rbA1 + (u32)((chA ^ rA1_7) << 4);
                u32 ah0[4], ah1[4];
                LDSM4(ah0, xh_s + a0);
                LDSM4(ah1, xh_s + a1);
                u32 bh[8];
                u32 cB = (u32)(((bcb + 2 * kc) ^ br7) << 4);
                #pragma unroll
                for (int p = 0; p < 2; p++) {
                    u32 rowB = (tapbase + brow + p * 16) * 128;
                    LDSM4(&bh[4 * p], bs_s + rowB + cB);
                }
                #pragma unroll
                for (int nf = 0; nf < 4; nf++) {
                    int bi = (nf >> 1) * 4 + (nf & 1) * 2;
                    MMA_FP16(acc[0][nf], ah0, bh[bi], bh[bi + 1]);
                    MMA_FP16(acc[1][nf], ah1, bh[bi], bh[bi + 1]);
                }
            }
        }
    }

    // --- epilogue: add bias, store --------------------------------------------
    int gg = lane >> 2, tig = lane & 3;
    #pragma unroll
    for (int mf = 0; mf < 2; mf++) {
        int h = h0 + 2 * hp + mf;
        #pragma unroll
        for (int nf = 0; nf < 4; nf++) {
            int co = coh + nf * 8 + tig * 2;
            float b0 = conv_b[co], b1 = conv_b[co + 1];
            size_t base = ((size_t)(n * C_OUT + co) * HH + h) * WW + w0;
            out[base + gg]                 = acc[mf][nf][0] + b0;
            out[base + HH * WW + gg]       = acc[mf][nf][1] + b1;
            out[base + gg + 8]             = acc[mf][nf][2] + b0;
            out[base + HH * WW + gg + 8]   = acc[mf][nf][3] + b1;
        }
    }
}

// ---------------- launch -----------------------------------------------------
extern "C" void kernel_launch(void* const* d_in, const int* in_sizes, int n_in,
                              void* d_out, int out_size) {
    const float* x      = (const float*)d_in[0];
    const float* weight = (const float*)d_in[1];
    const float* conv_w = (const float*)d_in[2];
    const float* conv_b = (const float*)d_in[3];
    const float* net0_w = (const float*)d_in[4];
    const float* net0_b = (const float*)d_in[5];
    const float* net1_w = (const float*)d_in[6];
    const float* net1_b = (const float*)d_in[7];
    const float* net2_w = (const float*)d_in[8];
    const float* net2_b = (const float*)d_in[9];
    float* out = (float*)d_out;

    static int smem_set = 0;
    if (!smem_set) {
        cudaFuncSetAttribute(conv_mma_kernel,
                             cudaFuncAttributeMaxDynamicSharedMemorySize, SMEM_BYTES);
        smem_set = 1;
    }

    class_sums_kernel<<<256, 256>>>(x);
    logits_softmax_kernel<<<1, 32>>>(net0_w, net0_b, net1_w, net1_b, net2_w, net2_b);
    agg_weights_kernel<<<NN * 8, 256>>>(weight, conv_w);
    conv_mma_kernel<<<dim3(WW / 16, HH / 8, NN), 256, SMEM_BYTES>>>(x, conv_b, out);
}

// round 11
// speedup vs baseline: 6.7958x; 1.2247x over previous
#include <cuda_runtime.h>
#include <cuda_fp16.h>
#include <math.h>

#define NN 8
#define C_IN 64
#define C_OUT 64
#define HH 128
#define WW 128
#define KK 4

typedef unsigned int u32;

// ---------------- scratch (device globals; no allocations allowed) ----------
__device__ float g_sums[NN][45];                 // zero at load; re-zeroed by conv kernel
__device__ __half g_wh[NN * 9 * C_OUT * C_IN];   // fused weight fp16, [n][tap][co][ci]

// ---------------- kernel 1: 45 class sums (quarter-channel warps, float4) ---
__global__ void class_sums_kernel(const float* __restrict__ x) {
    int gwarp = (blockIdx.x * blockDim.x + threadIdx.x) >> 5;   // 0..2047
    int lane = threadIdx.x & 31;
    int ch = gwarp >> 2, q = gwarp & 3;
    int n = ch >> 6, c = ch & 63;
    const float* p = x + (size_t)(n * C_IN + c) * (HH * WW);
    const float4* pr4 = (const float4*)(p + q * 32 * WW);

    float T = 0.f;
    #pragma unroll 4
    for (int i = lane; i < 32 * WW / 4; i += 32) {
        float4 v = pr4[i];
        T += (v.x + v.y) + (v.z + v.w);
    }
    float R0 = 0.f, RL = 0.f;
    if (q == 0) {
        float4 v = ((const float4*)p)[lane];
        R0 = (v.x + v.y) + (v.z + v.w);
    }
    if (q == 3) {
        float4 v = ((const float4*)(p + (HH - 1) * WW))[lane];
        RL = (v.x + v.y) + (v.z + v.w);
    }
    int h = q * 32 + lane;
    float C0 = p[h * WW], CL = p[h * WW + WW - 1];

    #pragma unroll
    for (int o = 16; o; o >>= 1) {
        T  += __shfl_xor_sync(0xffffffffu, T, o);
        R0 += __shfl_xor_sync(0xffffffffu, R0, o);
        RL += __shfl_xor_sync(0xffffffffu, RL, o);
        C0 += __shfl_xor_sync(0xffffffffu, C0, o);
        CL += __shfl_xor_sync(0xffffffffu, CL, o);
    }
    float c00 = (q == 0) ? p[0] : 0.f;
    float c0L = (q == 0) ? p[WW - 1] : 0.f;
    float cL0 = (q == 3) ? p[(HH - 1) * WW] : 0.f;
    float cLL = (q == 3) ? p[HH * WW - 1] : 0.f;
    float S[9];
    S[0] = c00;  S[2] = c0L;
    S[1] = R0 - c00 - c0L;
    S[6] = cL0;  S[8] = cLL;
    S[7] = RL - cL0 - cLL;
    S[3] = C0 - c00 - cL0;
    S[5] = CL - c0L - cLL;
    S[4] = T - R0 - RL - S[3] - S[5];
    int cd = (c == 0) ? 0 : (c == 1) ? 1 : (c == C_IN - 2) ? 3 : (c == C_IN - 1) ? 4 : 2;
    if (lane < 9) atomicAdd(&g_sums[n][cd * 9 + lane], S[lane]);
}

// ---------------- kernel 2: logits+softmax (inline) + fused weight -> fp16 --
__global__ __launch_bounds__(256)
void agg_weights_kernel(const float* __restrict__ weight,
                        const float* __restrict__ conv_w,
                        const float* __restrict__ net0_w,
                        const float* __restrict__ net0_b,
                        const float* __restrict__ net1_w,
                        const float* __restrict__ net1_b,
                        const float* __restrict__ net2_w,
                        const float* __restrict__ net2_b) {
    __shared__ float s[8 * 576];
    __shared__ float lg_s[KK];
    __shared__ float att_s[KK];
    int n = blockIdx.x >> 3;
    int cob = blockIdx.x & 7;                    // block of 8 co
    int tid = threadIdx.x;

    // --- logits from class sums (threads 0..3, read-only on g_sums) ----------
    if (tid < KK) {
        int k = tid;
        float S[5][3][3];
        #pragma unroll
        for (int i = 0; i < 45; i++) ((float*)S)[i] = g_sums[n][i];
        float Stot = 0.f;
        #pragma unroll
        for (int i = 0; i < 45; i++) Stot += ((float*)S)[i];

        const float mh[3][3]  = {{0,1,1},{1,1,1},{1,1,0}};
        const float m1d[3][5] = {{0,1,1,1,1},{1,1,1,1,1},{1,1,1,1,0}};
        const float m2d[5][5] = {{0,0,1,1,1},{0,1,1,1,1},{1,1,1,1,1},{1,1,1,1,0},{1,1,1,0,0}};
        const float invV = 1.0f / (float)(C_IN * HH * WW);

        float acc = net0_b[k] + net1_b[k] + net2_b[k] + net0_w[k] * Stot * invV;

        float s1 = 0.f;
        for (int td = 0; td < 3; td++) {
            float B[3][3];
            for (int chh = 0; chh < 3; chh++)
                for (int cw = 0; cw < 3; cw++) {
                    float v = 0.f;
                    for (int cd = 0; cd < 5; cd++) v += m1d[td][cd] * S[cd][chh][cw];
                    B[chh][cw] = v;
                }
            for (int th = 0; th < 3; th++)
                for (int tw = 0; tw < 3; tw++) {
                    float box = 0.f;
                    for (int chh = 0; chh < 3; chh++)
                        for (int cw = 0; cw < 3; cw++)
                            box += mh[th][chh] * mh[tw][cw] * B[chh][cw];
                    s1 += net1_w[k * 27 + td * 9 + th * 3 + tw] * box;
                }
        }
        float s2 = 0.f;
        for (int td = 0; td < 5; td++) {
            float B[3][3];
            for (int chh = 0; chh < 3; chh++)
                for (int cw = 0; cw < 3; cw++) {
                    float v = 0.f;
                    for (int cd = 0; cd < 5; cd++) v += m2d[td][cd] * S[cd][chh][cw];
                    B[chh][cw] = v;
                }
            for (int th = 0; th < 3; th++)
                for (int tw = 0; tw < 3; tw++) {
                    float box = 0.f;
                    for (int chh = 0; chh < 3; chh++)
                        for (int cw = 0; cw < 3; cw++)
                            box += mh[th][chh] * mh[tw][cw] * B[chh][cw];
                    s2 += net2_w[k * 45 + td * 9 + th * 3 + tw] * box;
                }
        }
        lg_s[k] = acc + (s1 + s2) * invV;
    }
    __syncthreads();
    if (tid < KK) {
        float m = lg_s[0];
        #pragma unroll
        for (int j = 1; j < KK; j++) m = fmaxf(m, lg_s[j]);
        float sum = 0.f;
        #pragma unroll
        for (int j = 0; j < KK; j++) sum += expf(lg_s[j] - m);
        att_s[tid] = expf(lg_s[tid] - m) / sum;
    }
    __syncthreads();

    float a0 = att_s[0], a1 = att_s[1], a2 = att_s[2], a3 = att_s[3];
    const int PER_K = C_OUT * C_IN * 9;
    int base = cob * 8 * 576;
    #pragma unroll
    for (int i = tid; i < 4608; i += 256) {
        float v = conv_w[base + i]
                + a0 * weight[0 * PER_K + base + i]
                + a1 * weight[1 * PER_K + base + i]
                + a2 * weight[2 * PER_K + base + i]
                + a3 * weight[3 * PER_K + base + i];
        s[i] = v;
    }
    __syncthreads();
    #pragma unroll
    for (int i = tid; i < 4608; i += 256) {
        int t = i / 512;
        int r = i - t * 512;
        int j = r >> 6, ci = r & 63;
        g_wh[(((size_t)n * 9 + t) * C_OUT + cob * 8 + j) * C_IN + ci] =
            __float2half_rn(s[(j * 64 + ci) * 9 + t]);
    }
}

// ---------------- kernel 3: tensor-core implicit-GEMM conv ------------------
__device__ __forceinline__ u32 su32(const void* p) {
    return (u32)__cvta_generic_to_shared(p);
}

#define LDSM4(R, ADDR)                                                         \
    asm volatile("ldmatrix.sync.aligned.m8n8.x4.shared.b16 {%0,%1,%2,%3}, [%4];" \
                 : "=r"((R)[0]), "=r"((R)[1]), "=r"((R)[2]), "=r"((R)[3])      \
                 : "r"(ADDR))

#define MMA_FP16(C, A, B0, B1)                                                 \
    asm volatile("mma.sync.aligned.m16n8k16.row.col.f32.f16.f16.f32 "         \
                 "{%0,%1,%2,%3}, {%4,%5,%6,%7}, {%8,%9}, {%0,%1,%2,%3};"      \
                 : "+f"((C)[0]), "+f"((C)[1]), "+f"((C)[2]), "+f"((C)[3])     \
                 : "r"((A)[0]), "r"((A)[1]), "r"((A)[2]), "r"((A)[3]),        \
                   "r"(B0), "r"(B1))

#define CP_ASYNC16(DST, SRC)                                                   \
    asm volatile("cp.async.cg.shared.global [%0], [%1], 16;" :: "r"(DST), "l"(SRC))
#define CP_ASYNC_WAIT()                                                        \
    asm volatile("cp.async.commit_group;\ncp.async.wait_group 0;" ::: "memory")

// Block: 128 threads (4 warps). Tile 8h x 16w x 64co; warp = h-pair, N_w=64.
// smem: xh 180 rows (10x18 halo) x 128B swizzled = 23040B
//       Bs  576 rows (9 taps x 64 co) x 128B     = 73728B  (all taps resident)
#define XS_BYTES (180 * 128)
#define SMEM_BYTES (XS_BYTES + 576 * 128)

__global__ __launch_bounds__(128, 2)
void conv_mma_kernel(const float* __restrict__ x,
                     const float* __restrict__ conv_b,
                     float* __restrict__ out) {
    extern __shared__ char sm[];
    char* xhb = sm;
    char* bsb = sm + XS_BYTES;
    u32 xh_s = su32(xhb), bs_s = su32(bsb);

    int w0 = blockIdx.x * 16, h0 = blockIdx.y * 8, n = blockIdx.z;
    int tid = threadIdx.x, hp = tid >> 5, lane = tid & 31;

    // designated block restores g_sums = 0 for the next run
    if (blockIdx.x == 0 && blockIdx.y == 0 && blockIdx.z == 0) {
        for (int i = tid; i < NN * 45; i += 128) ((float*)g_sums)[i] = 0.0f;
    }

    // --- B: all 9 taps via cp.async (16B, swizzled) ---------------------------
    const __half* whn = g_wh + (size_t)n * 9 * C_OUT * C_IN;
    #pragma unroll
    for (int i = tid; i < 4608; i += 128) {
        int tap = i >> 9;
        int r = i & 511;
        int co = r >> 3, q = r & 7;
        u32 dst = bs_s + (u32)(tap * C_OUT + co) * 128 + ((q ^ (co & 7)) << 4);
        CP_ASYNC16(dst, whn + ((size_t)(tap * C_OUT + co)) * C_IN + q * 8);
    }

    // --- x tile: thread per (pos, 8-ci chunk) -> one STS.128 ------------------
    const float* xn = x + (size_t)n * C_IN * HH * WW;
    #pragma unroll
    for (int i = tid; i < 180 * 8; i += 128) {
        int cib = i / 180;                       // 8-ci chunk index 0..7
        int pos = i - cib * 180;
        int r = pos / 18, c = pos - r * 18;
        int gh = h0 - 1 + r, gw = w0 - 1 + c;
        bool valid = (unsigned)gh < (unsigned)HH && (unsigned)gw < (unsigned)WW;
        const float* px = xn + (size_t)cib * 8 * (HH * WW) + gh * WW + gw;
        u32 pk[4];
        #pragma unroll
        for (int j = 0; j < 4; j++) {
            float v0 = valid ? px[(2 * j + 0) * (HH * WW)] : 0.f;
            float v1 = valid ? px[(2 * j + 1) * (HH * WW)] : 0.f;
            __half2 h2 = __floats2half2_rn(v0, v1);
            pk[j] = *(u32*)&h2;
        }
        u32 off = (u32)pos * 128 + ((cib ^ (pos & 7)) << 4);
        asm volatile("st.shared.v4.b32 [%0], {%1,%2,%3,%4};"
                     :: "r"(xh_s + off), "r"(pk[0]), "r"(pk[1]), "r"(pk[2]), "r"(pk[3]));
    }
    CP_ASYNC_WAIT();
    __syncthreads();

    float acc[2][8][4];
    #pragma unroll
    for (int mf = 0; mf < 2; mf++)
        #pragma unroll
        for (int nf = 0; nf < 8; nf++)
            #pragma unroll
            for (int r = 0; r < 4; r++) acc[mf][nf][r] = 0.f;

    // ldmatrix lane geometry (validated mapping)
    int arow = lane & 15;                        // A: w_local row
    int acb  = lane >> 4;                        // A: k chunk (0/1)
    int brow = (lane & 7) + ((lane >> 4) << 3);  // B: co row within 16
    int bcb  = (lane >> 3) & 1;                  // B: k chunk (0/1)
    int br7  = brow & 7;

    // --- barrier-free main loop: 9 taps x 4 kc --------------------------------
    #pragma unroll
    for (int g = 0; g < 3; g++) {                // kh
        #pragma unroll
        for (int tl = 0; tl < 3; tl++) {         // kw
            int rowA0 = (2 * hp + g) * 18 + arow + tl;
            int rowA1 = rowA0 + 18;
            u32 rbA0 = (u32)rowA0 * 128, rA0_7 = rowA0 & 7;
            u32 rbA1 = (u32)rowA1 * 128, rA1_7 = rowA1 & 7;
            u32 tapbase = (u32)((g * 3 + tl) * C_OUT);
            #pragma unroll
            for (int kc = 0; kc < 4; kc++) {
                int chA = acb + 2 * kc;
                u32 a0 = rbA0 + (u32)((chA ^ rA0_7) << 4);
                u32 a1 = rbA1 + (u32)((chA ^ rA1_7) << 4);
                u32 ah0[4], ah1[4];
                LDSM4(ah0, xh_s + a0);
                LDSM4(ah1, xh_s + a1);
                u32 bh[16];
                u32 cB = (u32)(((bcb + 2 * kc) ^ br7) << 4);
                #pragma unroll
                for (int p = 0; p < 4; p++) {
                    u32 rowB = (tapbase + brow + p * 16) * 128;
                    LDSM4(&bh[4 * p], bs_s + rowB + cB);
                }
                #pragma unroll
                for (int nf = 0; nf < 8; nf++) {
                    int bi = (nf >> 1) * 4 + (nf & 1) * 2;
                    MMA_FP16(acc[0][nf], ah0, bh[bi], bh[bi + 1]);
                    MMA_FP16(acc[1][nf], ah1, bh[bi], bh[bi + 1]);
                }
            }
        }
    }

    // --- epilogue: add bias, store --------------------------------------------
    int gg = lane >> 2, tig = lane & 3;
    #pragma unroll
    for (int mf = 0; mf < 2; mf++) {
        int h = h0 + 2 * hp + mf;
        #pragma unroll
        for (int nf = 0; nf < 8; nf++) {
            int co = nf * 8 + tig * 2;
            float b0 = conv_b[co], b1 = conv_b[co + 1];
            size_t base = ((size_t)(n * C_OUT + co) * HH + h) * WW + w0;
            out[base + gg]                 = acc[mf][nf][0] + b0;
            out[base + HH * WW + gg]       = acc[mf][nf][1] + b1;
            out[base + gg + 8]             = acc[mf][nf][2] + b0;
            out[base + HH * WW + gg + 8]   = acc[mf][nf][3] + b1;
        }
    }
}

// ---------------- launch -----------------------------------------------------
extern "C" void kernel_launch(void* const* d_in, const int* in_sizes, int n_in,
                              void* d_out, int out_size) {
    const float* x      = (const float*)d_in[0];
    const float* weight = (const float*)d_in[1];
    const float* conv_w = (const float*)d_in[2];
    const float* conv_b = (const float*)d_in[3];
    const float* net0_w = (const float*)d_in[4];
    const float* net0_b = (const float*)d_in[5];
    const float* net1_w = (const float*)d_in[6];
    const float* net1_b = (const float*)d_in[7];
    const float* net2_w = (const float*)d_in[8];
    const float* net2_b = (const float*)d_in[9];
    float* out = (float*)d_out;

    static int smem_set = 0;
    if (!smem_set) {
        cudaFuncSetAttribute(conv_mma_kernel,
                             cudaFuncAttributeMaxDynamicSharedMemorySize, SMEM_BYTES);
        smem_set = 1;
    }

    class_sums_kernel<<<256, 256>>>(x);
    agg_weights_kernel<<<NN * 8, 256>>>(weight, conv_w, net0_w, net0_b,
                                        net1_w, net1_b, net2_w, net2_b);
    conv_mma_kernel<<<dim3(WW / 16, HH / 8, NN), 128, SMEM_BYTES>>>(x, conv_b, out);
}